// round 4
// baseline (speedup 1.0000x reference)
#include <cuda_runtime.h>
#include <cuda_fp16.h>
#include <math.h>

#define BB 4
#define NN 8192
#define KK 32
#define BN (BB*NN)
#define PT 8
#define NWARP 8
#define NT8 (BN/PT)

typedef unsigned long long u64;

// scratch (device globals; no allocation)
__device__ uint2   g_F1ab[BN*32];   // per point: {a-pair, b-pair} fp16, pair=(dim2L,dim2L+1)
__device__ __half2 g_F1c[BN*32];
__device__ float   g_z[BN*64];
__device__ float   g_rh[BN*64];

__device__ __forceinline__ float lrelu(float v){ return v > 0.f ? v : 0.1f*v; }
__device__ __forceinline__ float sigm(float v){ return 1.f/(1.f+expf(-v)); }
__device__ __forceinline__ u64 pk2(float lo, float hi){
    u64 d; asm("mov.b64 %0, {%1,%2};" : "=l"(d) : "f"(lo), "f"(hi)); return d;
}
__device__ __forceinline__ float2 upk(u64 v){
    float2 r; asm("mov.b64 {%0,%1}, %2;" : "=f"(r.x), "=f"(r.y) : "l"(v)); return r;
}
// Blackwell packed fp32 FMA (SASS FFMA2): two fp32 fma in one instruction. Exact fp32.
__device__ __forceinline__ u64 ffma2(u64 a, u64 b, u64 c){
    u64 d; asm("fma.rn.f32x2 %0, %1, %2, %3;" : "=l"(d) : "l"(a), "l"(b), "l"(c)); return d;
}

// pack weight rows 2jp,2jp+1 for lane l: {W[2jp][2l],W[2jp][2l+1],W[2jp+1][2l],W[2jp+1][2l+1]}
__device__ __forceinline__ float4 packW(const float* S, int jp, int l){
    float4 v;
    v.x = S[(2*jp)*64 + 2*l];     v.y = S[(2*jp)*64 + 2*l + 1];
    v.z = S[(2*jp+1)*64 + 2*l];   v.w = S[(2*jp+1)*64 + 2*l + 1];
    return v;
}

// ---------------- linear2: F1ab = [h|x] @ {W1a[0], W1a[1]}, packed fp16 out ----------------
__global__ void linear2_kernel(const float* __restrict__ s0, const float* __restrict__ s1,
                               const float* __restrict__ W1, uint2* __restrict__ oAB)
{
    extern __shared__ ulonglong2 smu[];
    // weights: Wa [0,2048), Wb [2048,4096); staging: 4096 + w*512, slot(q,cp)=q*64+cp
    int tid = threadIdx.x, w = tid>>5, L = tid&31;
    const float* Wa = W1;
    const float* Wb = W1 + 131*64;
    for (int i = tid; i < 4096; i += blockDim.x) {
        int arr = i >> 11, rem = i & 2047, cp = rem >> 5, l = rem & 31;
        ((float4*)smu)[i] = packW(arr ? Wb : Wa, cp, l);
    }
    __syncthreads();
    const ulonglong2* sWa = smu;
    const ulonglong2* sWb = smu + 2048;
    ulonglong2* stg = smu + 4096 + w*512;
    for (int t = blockIdx.x*NWARP + w; t < NT8; t += gridDim.x*NWARP) {
        int p0 = t*PT;
        #pragma unroll
        for (int q = 0; q < PT; q++) {
            int p = p0 + q;
            float2 fa = *(const float2*)&s0[(size_t)p*64 + 2*L];
            float2 fb = *(const float2*)&s1[(size_t)p*64 + 2*L];
            ((float4*)stg)[q*64 + L]      = make_float4(fa.x, fa.x, fa.y, fa.y);
            ((float4*)stg)[q*64 + 32 + L] = make_float4(fb.x, fb.x, fb.y, fb.y);
        }
        __syncwarp();
        u64 accA[PT], accB[PT];
        #pragma unroll
        for (int q = 0; q < PT; q++) { accA[q] = 0ull; accB[q] = 0ull; }
        #pragma unroll 8
        for (int cp = 0; cp < 64; cp++) {
            ulonglong2 wa = sWa[cp*32 + L];
            ulonglong2 wb = sWb[cp*32 + L];
            #pragma unroll
            for (int q = 0; q < PT; q++) {
                ulonglong2 a = stg[q*64 + cp];
                accA[q] = ffma2(a.x, wa.x, accA[q]);
                accA[q] = ffma2(a.y, wa.y, accA[q]);
                accB[q] = ffma2(a.x, wb.x, accB[q]);
                accB[q] = ffma2(a.y, wb.y, accB[q]);
            }
        }
        #pragma unroll
        for (int q = 0; q < PT; q++) {
            float2 ra = upk(accA[q]), rb = upk(accB[q]);
            __half2 ha = __floats2half2_rn(ra.x, ra.y);
            __half2 hb = __floats2half2_rn(rb.x, rb.y);
            uint2 o;
            o.x = *(const unsigned int*)&ha;
            o.y = *(const unsigned int*)&hb;
            oAB[(size_t)(p0+q)*32 + L] = o;
        }
        __syncwarp();
    }
}

// ---------------- linear1: F1c = [rh|x] @ W1a[2], fp16 out ----------------
__global__ void linear1_kernel(const float* __restrict__ s0, const float* __restrict__ s1,
                               const float* __restrict__ W1, __half2* __restrict__ oC)
{
    extern __shared__ ulonglong2 smu[];
    // weights Wc [0,2048); staging 2048 + w*512
    int tid = threadIdx.x, w = tid>>5, L = tid&31;
    const float* Wc = W1 + 2*131*64;
    for (int i = tid; i < 2048; i += blockDim.x) {
        int cp = i >> 5, l = i & 31;
        ((float4*)smu)[i] = packW(Wc, cp, l);
    }
    __syncthreads();
    const ulonglong2* sWc = smu;
    ulonglong2* stg = smu + 2048 + w*512;
    for (int t = blockIdx.x*NWARP + w; t < NT8; t += gridDim.x*NWARP) {
        int p0 = t*PT;
        #pragma unroll
        for (int q = 0; q < PT; q++) {
            int p = p0 + q;
            float2 fa = *(const float2*)&s0[(size_t)p*64 + 2*L];
            float2 fb = *(const float2*)&s1[(size_t)p*64 + 2*L];
            ((float4*)stg)[q*64 + L]      = make_float4(fa.x, fa.x, fa.y, fa.y);
            ((float4*)stg)[q*64 + 32 + L] = make_float4(fb.x, fb.x, fb.y, fb.y);
        }
        __syncwarp();
        u64 acc[PT];
        #pragma unroll
        for (int q = 0; q < PT; q++) acc[q] = 0ull;
        #pragma unroll 8
        for (int cp = 0; cp < 64; cp++) {
            ulonglong2 wc = sWc[cp*32 + L];
            #pragma unroll
            for (int q = 0; q < PT; q++) {
                ulonglong2 a = stg[q*64 + cp];
                acc[q] = ffma2(a.x, wc.x, acc[q]);
                acc[q] = ffma2(a.y, wc.y, acc[q]);
            }
        }
        #pragma unroll
        for (int q = 0; q < PT; q++) {
            float2 r = upk(acc[q]);
            oC[(size_t)(p0+q)*32 + L] = __floats2half2_rn(r.x, r.y);
        }
        __syncwarp();
    }
}

// ---------------- gate01: branches 0+1 -> z, r*h ----------------
__global__ void gate01_kernel(const float* __restrict__ h,
    const float* __restrict__ W1, const float* __restrict__ b1,
    const float* __restrict__ W2, const float* __restrict__ b2,
    const float* __restrict__ W3, const float* __restrict__ b3,
    const int* __restrict__ nidx, const float* __restrict__ ef,
    float* __restrict__ z_out, float* __restrict__ rh_out)
{
    extern __shared__ ulonglong2 smu[];
    // W2a [0,1024) W2b [1024,2048) W3a [2048,3072) W3b [3072,4096); staging 4096 + w*512
    int tid = threadIdx.x, w = tid>>5, L = tid&31;
    for (int i = tid; i < 4096; i += blockDim.x) {
        int arr = i >> 10, rem = i & 1023, jp = rem >> 5, l = rem & 31;
        const float* S = (arr == 0) ? W2 : (arr == 1) ? (W2 + 4096)
                       : (arr == 2) ? W3 : (W3 + 4096);
        ((float4*)smu)[i] = packW(S, jp, l);
    }
    __syncthreads();
    const ulonglong2* sW2a = smu;
    const ulonglong2* sW2b = smu + 1024;
    const ulonglong2* sW3a = smu + 2048;
    const ulonglong2* sW3b = smu + 3072;
    ulonglong2* stgA = smu + 4096 + w*512;      // 256 ull2
    ulonglong2* stgB = stgA + 256;

    const float* eWa = W1 + 128*64;
    const float* eWb = W1 + 131*64 + 128*64;
    __half2 wA[3], wB[3];
    #pragma unroll
    for (int j = 0; j < 3; j++) {
        wA[j] = __floats2half2_rn(eWa[j*64 + 2*L], eWa[j*64 + 2*L + 1]);
        wB[j] = __floats2half2_rn(eWb[j*64 + 2*L], eWb[j*64 + 2*L + 1]);
    }
    float2 b1a = *(const float2*)&b1[2*L],      b1b = *(const float2*)&b1[64 + 2*L];
    float2 b2a = *(const float2*)&b2[2*L],      b2b = *(const float2*)&b2[64 + 2*L];
    float2 b3a = *(const float2*)&b3[2*L],      b3b = *(const float2*)&b3[64 + 2*L];
    u64 i2a = pk2(b2a.x, b2a.y), i2b = pk2(b2b.x, b2b.y);
    u64 i3a = pk2(b3a.x, b3a.y), i3b = pk2(b3b.x, b3b.y);

    for (int t = blockIdx.x*NWARP + w; t < NT8; t += gridDim.x*NWARP) {
        int p0 = t*PT;
        int bb = p0 >> 13;
        const uint2* Fab = g_F1ab + (size_t)bb*NN*32;
        #pragma unroll
        for (int q = 0; q < PT; q++) {
            int p = p0 + q;
            int ii = nidx[(size_t)p*KK + L];
            unsigned e01, e2d;
            {
                const float* ep = ef + (size_t)p*96 + 3*L;
                __half2 t01 = __floats2half2_rn(ep[0], ep[1]);
                __half2 t2  = __float2half2_rn(ep[2]);
                e01 = *(const unsigned*)&t01;
                e2d = *(const unsigned*)&t2;
            }
            __half2 ma = __float2half2_rn(-6.0e4f), mb = ma;
            #pragma unroll 8
            for (int k = 0; k < KK; k++) {
                int fi       = __shfl_sync(0xffffffffu, ii,  k);
                unsigned p01 = __shfl_sync(0xffffffffu, e01, k);
                unsigned p2  = __shfl_sync(0xffffffffu, e2d, k);
                __half2 he01 = *(const __half2*)&p01;
                __half2 h0 = __low2half2(he01), h1 = __high2half2(he01);
                __half2 h2v = *(const __half2*)&p2;
                uint2 v = __ldg(&Fab[(size_t)fi*32 + L]);
                __half2 ta = *(const __half2*)&v.x;
                ta = __hfma2(h0, wA[0], ta);
                ta = __hfma2(h1, wA[1], ta);
                ta = __hfma2(h2v, wA[2], ta);
                ma = __hmax2(ma, ta);
                __half2 tb = *(const __half2*)&v.y;
                tb = __hfma2(h0, wB[0], tb);
                tb = __hfma2(h1, wB[1], tb);
                tb = __hfma2(h2v, wB[2], tb);
                mb = __hmax2(mb, tb);
            }
            float2 fa = __half22float2(ma), fb = __half22float2(mb);
            fa.x = lrelu(fa.x + b1a.x);  fa.y = lrelu(fa.y + b1a.y);
            fb.x = lrelu(fb.x + b1b.x);  fb.y = lrelu(fb.y + b1b.y);
            ((float4*)stgA)[q*32 + L] = make_float4(fa.x, fa.x, fa.y, fa.y);
            ((float4*)stgB)[q*32 + L] = make_float4(fb.x, fb.x, fb.y, fb.y);
        }
        __syncwarp();
        // layer 1
        u64 ya[PT], yb[PT];
        #pragma unroll
        for (int q = 0; q < PT; q++) { ya[q] = i2a; yb[q] = i2b; }
        #pragma unroll 4
        for (int jp = 0; jp < 32; jp++) {
            ulonglong2 wa = sW2a[jp*32 + L];
            ulonglong2 wb = sW2b[jp*32 + L];
            #pragma unroll
            for (int q = 0; q < PT; q++) {
                ulonglong2 aa = stgA[q*32 + jp];
                ulonglong2 ab = stgB[q*32 + jp];
                ya[q] = ffma2(aa.x, wa.x, ya[q]);
                ya[q] = ffma2(aa.y, wa.y, ya[q]);
                yb[q] = ffma2(ab.x, wb.x, yb[q]);
                yb[q] = ffma2(ab.y, wb.y, yb[q]);
            }
        }
        __syncwarp();
        #pragma unroll
        for (int q = 0; q < PT; q++) {
            float2 A = upk(ya[q]), Bv = upk(yb[q]);
            A.x = lrelu(A.x);  A.y = lrelu(A.y);
            Bv.x = lrelu(Bv.x); Bv.y = lrelu(Bv.y);
            ((float4*)stgA)[q*32 + L] = make_float4(A.x, A.x, A.y, A.y);
            ((float4*)stgB)[q*32 + L] = make_float4(Bv.x, Bv.x, Bv.y, Bv.y);
        }
        __syncwarp();
        // layer 2
        u64 oa[PT], ob[PT];
        #pragma unroll
        for (int q = 0; q < PT; q++) { oa[q] = i3a; ob[q] = i3b; }
        #pragma unroll 4
        for (int jp = 0; jp < 32; jp++) {
            ulonglong2 wa = sW3a[jp*32 + L];
            ulonglong2 wb = sW3b[jp*32 + L];
            #pragma unroll
            for (int q = 0; q < PT; q++) {
                ulonglong2 aa = stgA[q*32 + jp];
                ulonglong2 ab = stgB[q*32 + jp];
                oa[q] = ffma2(aa.x, wa.x, oa[q]);
                oa[q] = ffma2(aa.y, wa.y, oa[q]);
                ob[q] = ffma2(ab.x, wb.x, ob[q]);
                ob[q] = ffma2(ab.y, wb.y, ob[q]);
            }
        }
        #pragma unroll
        for (int q = 0; q < PT; q++) {
            int p = p0 + q;
            float2 A = upk(oa[q]), Bv = upk(ob[q]);
            float z0 = sigm(A.x), z1 = sigm(A.y);
            *(float2*)&z_out[(size_t)p*64 + 2*L] = make_float2(z0, z1);
            float r0 = sigm(Bv.x), r1 = sigm(Bv.y);
            float2 hv = *(const float2*)&h[(size_t)p*64 + 2*L];
            *(float2*)&rh_out[(size_t)p*64 + 2*L] = make_float2(r0*hv.x, r1*hv.y);
        }
        __syncwarp();
    }
}

// ---------------- gate2: branch 2 -> q; out = h + z*(q-h) ----------------
__global__ void gate2_kernel(const float* __restrict__ h,
    const float* __restrict__ W1, const float* __restrict__ b1,
    const float* __restrict__ W2, const float* __restrict__ b2,
    const float* __restrict__ W3, const float* __restrict__ b3,
    const int* __restrict__ nidx, const float* __restrict__ ef,
    float* __restrict__ out)
{
    extern __shared__ ulonglong2 smu[];
    // W2c [0,1024) W3c [1024,2048); staging 2048 + w*256
    int tid = threadIdx.x, w = tid>>5, L = tid&31;
    for (int i = tid; i < 2048; i += blockDim.x) {
        int arr = i >> 10, rem = i & 1023, jp = rem >> 5, l = rem & 31;
        const float* S = arr ? (W3 + 2*4096) : (W2 + 2*4096);
        ((float4*)smu)[i] = packW(S, jp, l);
    }
    __syncthreads();
    const ulonglong2* sW2c = smu;
    const ulonglong2* sW3c = smu + 1024;
    ulonglong2* stg = smu + 2048 + w*256;

    const float* eWc = W1 + 2*131*64 + 128*64;
    __half2 wC[3];
    #pragma unroll
    for (int j = 0; j < 3; j++)
        wC[j] = __floats2half2_rn(eWc[j*64 + 2*L], eWc[j*64 + 2*L + 1]);
    float2 b1c = *(const float2*)&b1[128 + 2*L];
    float2 b2c = *(const float2*)&b2[128 + 2*L];
    float2 b3c = *(const float2*)&b3[128 + 2*L];
    u64 i2c = pk2(b2c.x, b2c.y), i3c = pk2(b3c.x, b3c.y);

    for (int t = blockIdx.x*NWARP + w; t < NT8; t += gridDim.x*NWARP) {
        int p0 = t*PT;
        int bb = p0 >> 13;
        const __half2* Fc = g_F1c + (size_t)bb*NN*32;
        #pragma unroll
        for (int q = 0; q < PT; q++) {
            int p = p0 + q;
            int ii = nidx[(size_t)p*KK + L];
            unsigned e01, e2d;
            {
                const float* ep = ef + (size_t)p*96 + 3*L;
                __half2 t01 = __floats2half2_rn(ep[0], ep[1]);
                __half2 t2  = __float2half2_rn(ep[2]);
                e01 = *(const unsigned*)&t01;
                e2d = *(const unsigned*)&t2;
            }
            __half2 mc = __float2half2_rn(-6.0e4f);
            #pragma unroll 8
            for (int k = 0; k < KK; k++) {
                int fi       = __shfl_sync(0xffffffffu, ii,  k);
                unsigned p01 = __shfl_sync(0xffffffffu, e01, k);
                unsigned p2  = __shfl_sync(0xffffffffu, e2d, k);
                __half2 he01 = *(const __half2*)&p01;
                __half2 h0 = __low2half2(he01), h1 = __high2half2(he01);
                __half2 h2v = *(const __half2*)&p2;
                __half2 v = __ldg(&Fc[(size_t)fi*32 + L]);
                v = __hfma2(h0, wC[0], v);
                v = __hfma2(h1, wC[1], v);
                v = __hfma2(h2v, wC[2], v);
                mc = __hmax2(mc, v);
            }
            float2 fc = __half22float2(mc);
            fc.x = lrelu(fc.x + b1c.x);  fc.y = lrelu(fc.y + b1c.y);
            ((float4*)stg)[q*32 + L] = make_float4(fc.x, fc.x, fc.y, fc.y);
        }
        __syncwarp();
        u64 yc[PT];
        #pragma unroll
        for (int q = 0; q < PT; q++) yc[q] = i2c;
        #pragma unroll 4
        for (int jp = 0; jp < 32; jp++) {
            ulonglong2 wc = sW2c[jp*32 + L];
            #pragma unroll
            for (int q = 0; q < PT; q++) {
                ulonglong2 a = stg[q*32 + jp];
                yc[q] = ffma2(a.x, wc.x, yc[q]);
                yc[q] = ffma2(a.y, wc.y, yc[q]);
            }
        }
        __syncwarp();
        #pragma unroll
        for (int q = 0; q < PT; q++) {
            float2 A = upk(yc[q]);
            A.x = lrelu(A.x);  A.y = lrelu(A.y);
            ((float4*)stg)[q*32 + L] = make_float4(A.x, A.x, A.y, A.y);
        }
        __syncwarp();
        u64 oc[PT];
        #pragma unroll
        for (int q = 0; q < PT; q++) oc[q] = i3c;
        #pragma unroll 4
        for (int jp = 0; jp < 32; jp++) {
            ulonglong2 wc = sW3c[jp*32 + L];
            #pragma unroll
            for (int q = 0; q < PT; q++) {
                ulonglong2 a = stg[q*32 + jp];
                oc[q] = ffma2(a.x, wc.x, oc[q]);
                oc[q] = ffma2(a.y, wc.y, oc[q]);
            }
        }
        #pragma unroll
        for (int q = 0; q < PT; q++) {
            int p = p0 + q;
            float2 A = upk(oc[q]);
            float q0 = tanhf(A.x), q1 = tanhf(A.y);
            float2 zv = *(const float2*)&g_z[(size_t)p*64 + 2*L];
            float2 hv = *(const float2*)&h[(size_t)p*64 + 2*L];
            float o0 = hv.x + zv.x*(q0 - hv.x);
            float o1 = hv.y + zv.y*(q1 - hv.y);
            *(float2*)&out[(size_t)p*64 + 2*L] = make_float2(o0, o1);
        }
        __syncwarp();
    }
}

extern "C" void kernel_launch(void* const* d_in, const int* in_sizes, int n_in,
                              void* d_out, int out_size)
{
    const float* h   = (const float*)d_in[0];
    const float* x   = (const float*)d_in[1];
    // d_in[2] = c, unused (matches reference)
    const float* W1  = (const float*)d_in[3];
    const float* b1  = (const float*)d_in[4];
    const float* W2  = (const float*)d_in[5];
    const float* b2  = (const float*)d_in[6];
    const float* W3  = (const float*)d_in[7];
    const float* b3  = (const float*)d_in[8];
    const int*   nidx = (const int*)d_in[9];
    const float* ef  = (const float*)d_in[10];
    float* out = (float*)d_out;

    void *pF1ab, *pF1c, *pz, *prh;
    cudaGetSymbolAddress(&pF1ab, g_F1ab);
    cudaGetSymbolAddress(&pF1c,  g_F1c);
    cudaGetSymbolAddress(&pz,    g_z);
    cudaGetSymbolAddress(&prh,   g_rh);

    const int smem_lin2 = (4096 + 8*512) * 16;   // 131072
    const int smem_lin1 = (2048 + 8*512) * 16;   // 98304
    const int smem_g01  = (4096 + 8*512) * 16;   // 131072
    const int smem_g2   = (2048 + 8*256) * 16;   // 65536

    cudaFuncSetAttribute(linear2_kernel, cudaFuncAttributeMaxDynamicSharedMemorySize, smem_lin2);
    cudaFuncSetAttribute(linear1_kernel, cudaFuncAttributeMaxDynamicSharedMemorySize, smem_lin1);
    cudaFuncSetAttribute(gate01_kernel,  cudaFuncAttributeMaxDynamicSharedMemorySize, smem_g01);
    cudaFuncSetAttribute(gate2_kernel,   cudaFuncAttributeMaxDynamicSharedMemorySize, smem_g2);

    dim3 blk(256);

    // F1ab = [h|x] @ {W1a[0], W1a[1]}  (packed fp16)
    linear2_kernel<<<148, blk, smem_lin2>>>(h, x, W1, (uint2*)pF1ab);
    // z, r*h
    gate01_kernel<<<148, blk, smem_g01>>>(h, W1, b1, W2, b2, W3, b3, nidx, ef,
                                          (float*)pz, (float*)prh);
    // F1c = [r*h|x] @ W1a[2]  (fp16)
    linear1_kernel<<<296, blk, smem_lin1>>>((const float*)prh, x, W1, (__half2*)pF1c);
    // q and final output
    gate2_kernel<<<444, blk, smem_g2>>>(h, W1, b1, W2, b2, W3, b3, nidx, ef, out);
}

// round 5
// speedup vs baseline: 1.0342x; 1.0342x over previous
#include <cuda_runtime.h>
#include <cuda_fp16.h>
#include <math.h>

#define BB 4
#define NN 8192
#define KK 32
#define BN (BB*NN)
#define NWARP 16
#define NT2 (BN/2)
#define NT4 (BN/4)

typedef unsigned long long u64;

// scratch (device globals; no allocation)
__device__ uint2   g_F1ab[BN*32];   // per point: {a-pair, b-pair} fp16, pair=(dim2L,dim2L+1)
__device__ __half2 g_F1c[BN*32];
__device__ float   g_z[BN*64];
__device__ float   g_rh[BN*64];

__device__ __forceinline__ float lrelu(float v){ return v > 0.f ? v : 0.1f*v; }
__device__ __forceinline__ float sigm(float v){ return 1.f/(1.f+expf(-v)); }
__device__ __forceinline__ u64 pk2(float lo, float hi){
    u64 d; asm("mov.b64 %0, {%1,%2};" : "=l"(d) : "f"(lo), "f"(hi)); return d;
}
__device__ __forceinline__ float2 upk(u64 v){
    float2 r; asm("mov.b64 {%0,%1}, %2;" : "=f"(r.x), "=f"(r.y) : "l"(v)); return r;
}
// Blackwell packed fp32 FMA (SASS FFMA2): two fp32 fma in one instruction. Exact fp32.
__device__ __forceinline__ u64 ffma2(u64 a, u64 b, u64 c){
    u64 d; asm("fma.rn.f32x2 %0, %1, %2, %3;" : "=l"(d) : "l"(a), "l"(b), "l"(c)); return d;
}

// pack weight rows 2jp,2jp+1 for lane l: {W[2jp][2l],W[2jp][2l+1],W[2jp+1][2l],W[2jp+1][2l+1]}
__device__ __forceinline__ float4 packW(const float* S, int jp, int l){
    float4 v;
    v.x = S[(2*jp)*64 + 2*l];     v.y = S[(2*jp)*64 + 2*l + 1];
    v.z = S[(2*jp+1)*64 + 2*l];   v.w = S[(2*jp+1)*64 + 2*l + 1];
    return v;
}

// ---------------- linear2: F1ab = [h|x] @ {W1a[0], W1a[1]}, packed fp16 out ----------------
__global__ void __launch_bounds__(512, 2)
linear2_kernel(const float* __restrict__ s0, const float* __restrict__ s1,
               const float* __restrict__ W1, uint2* __restrict__ oAB)
{
    extern __shared__ ulonglong2 smu[];
    // Wa [0,2048) Wb [2048,4096); staging 4096 + w*128  (slot q*64+cp)
    int tid = threadIdx.x, w = tid>>5, L = tid&31;
    const float* Wa = W1;
    const float* Wb = W1 + 131*64;
    for (int i = tid; i < 4096; i += blockDim.x) {
        int arr = i >> 11, rem = i & 2047, cp = rem >> 5, l = rem & 31;
        ((float4*)smu)[i] = packW(arr ? Wb : Wa, cp, l);
    }
    __syncthreads();
    const ulonglong2* sWa = smu;
    const ulonglong2* sWb = smu + 2048;
    ulonglong2* stg = smu + 4096 + w*128;
    for (int t = blockIdx.x*NWARP + w; t < NT2; t += gridDim.x*NWARP) {
        int p0 = t*2;
        #pragma unroll
        for (int q = 0; q < 2; q++) {
            int p = p0 + q;
            float2 fa = *(const float2*)&s0[(size_t)p*64 + 2*L];
            float2 fb = *(const float2*)&s1[(size_t)p*64 + 2*L];
            ((float4*)stg)[q*64 + L]      = make_float4(fa.x, fa.x, fa.y, fa.y);
            ((float4*)stg)[q*64 + 32 + L] = make_float4(fb.x, fb.x, fb.y, fb.y);
        }
        __syncwarp();
        u64 accA[2], accB[2];
        #pragma unroll
        for (int q = 0; q < 2; q++) { accA[q] = 0ull; accB[q] = 0ull; }
        #pragma unroll 8
        for (int cp = 0; cp < 64; cp++) {
            ulonglong2 wa = sWa[cp*32 + L];
            ulonglong2 wb = sWb[cp*32 + L];
            #pragma unroll
            for (int q = 0; q < 2; q++) {
                ulonglong2 a = stg[q*64 + cp];
                accA[q] = ffma2(a.x, wa.x, accA[q]);
                accA[q] = ffma2(a.y, wa.y, accA[q]);
                accB[q] = ffma2(a.x, wb.x, accB[q]);
                accB[q] = ffma2(a.y, wb.y, accB[q]);
            }
        }
        #pragma unroll
        for (int q = 0; q < 2; q++) {
            float2 ra = upk(accA[q]), rb = upk(accB[q]);
            __half2 ha = __floats2half2_rn(ra.x, ra.y);
            __half2 hb = __floats2half2_rn(rb.x, rb.y);
            uint2 o;
            o.x = *(const unsigned int*)&ha;
            o.y = *(const unsigned int*)&hb;
            oAB[(size_t)(p0+q)*32 + L] = o;
        }
        __syncwarp();
    }
}

// ---------------- linear1: F1c = [rh|x] @ W1a[2], fp16 out ----------------
__global__ void __launch_bounds__(512, 2)
linear1_kernel(const float* __restrict__ s0, const float* __restrict__ s1,
               const float* __restrict__ W1, __half2* __restrict__ oC)
{
    extern __shared__ ulonglong2 smu[];
    // Wc [0,2048); staging 2048 + w*128
    int tid = threadIdx.x, w = tid>>5, L = tid&31;
    const float* Wc = W1 + 2*131*64;
    for (int i = tid; i < 2048; i += blockDim.x) {
        int cp = i >> 5, l = i & 31;
        ((float4*)smu)[i] = packW(Wc, cp, l);
    }
    __syncthreads();
    const ulonglong2* sWc = smu;
    ulonglong2* stg = smu + 2048 + w*128;
    for (int t = blockIdx.x*NWARP + w; t < NT2; t += gridDim.x*NWARP) {
        int p0 = t*2;
        #pragma unroll
        for (int q = 0; q < 2; q++) {
            int p = p0 + q;
            float2 fa = *(const float2*)&s0[(size_t)p*64 + 2*L];
            float2 fb = *(const float2*)&s1[(size_t)p*64 + 2*L];
            ((float4*)stg)[q*64 + L]      = make_float4(fa.x, fa.x, fa.y, fa.y);
            ((float4*)stg)[q*64 + 32 + L] = make_float4(fb.x, fb.x, fb.y, fb.y);
        }
        __syncwarp();
        u64 acc[2];
        acc[0] = 0ull; acc[1] = 0ull;
        #pragma unroll 8
        for (int cp = 0; cp < 64; cp++) {
            ulonglong2 wc = sWc[cp*32 + L];
            #pragma unroll
            for (int q = 0; q < 2; q++) {
                ulonglong2 a = stg[q*64 + cp];
                acc[q] = ffma2(a.x, wc.x, acc[q]);
                acc[q] = ffma2(a.y, wc.y, acc[q]);
            }
        }
        #pragma unroll
        for (int q = 0; q < 2; q++) {
            float2 r = upk(acc[q]);
            oC[(size_t)(p0+q)*32 + L] = __floats2half2_rn(r.x, r.y);
        }
        __syncwarp();
    }
}

// ---------------- gate01: branches 0+1 -> z, r*h ----------------
__global__ void __launch_bounds__(512, 2)
gate01_kernel(const float* __restrict__ h,
    const float* __restrict__ W1, const float* __restrict__ b1,
    const float* __restrict__ W2, const float* __restrict__ b2,
    const float* __restrict__ W3, const float* __restrict__ b3,
    const int* __restrict__ nidx, const float* __restrict__ ef,
    float* __restrict__ z_out, float* __restrict__ rh_out)
{
    extern __shared__ ulonglong2 smu[];
    // W2a [0,1024) W2b [1024,2048) W3a [2048,3072) W3b [3072,4096); staging 4096 + w*128
    int tid = threadIdx.x, w = tid>>5, L = tid&31;
    for (int i = tid; i < 4096; i += blockDim.x) {
        int arr = i >> 10, rem = i & 1023, jp = rem >> 5, l = rem & 31;
        const float* S = (arr == 0) ? W2 : (arr == 1) ? (W2 + 4096)
                       : (arr == 2) ? W3 : (W3 + 4096);
        ((float4*)smu)[i] = packW(S, jp, l);
    }
    __syncthreads();
    const ulonglong2* sW2a = smu;
    const ulonglong2* sW2b = smu + 1024;
    const ulonglong2* sW3a = smu + 2048;
    const ulonglong2* sW3b = smu + 3072;
    ulonglong2* stgA = smu + 4096 + w*128;   // 2 pts x 32 jp
    ulonglong2* stgB = stgA + 64;

    const float* eWa = W1 + 128*64;
    const float* eWb = W1 + 131*64 + 128*64;
    __half2 wA[3], wB[3];
    #pragma unroll
    for (int j = 0; j < 3; j++) {
        wA[j] = __floats2half2_rn(eWa[j*64 + 2*L], eWa[j*64 + 2*L + 1]);
        wB[j] = __floats2half2_rn(eWb[j*64 + 2*L], eWb[j*64 + 2*L + 1]);
    }
    float2 b1a = *(const float2*)&b1[2*L],      b1b = *(const float2*)&b1[64 + 2*L];
    float2 b2a = *(const float2*)&b2[2*L],      b2b = *(const float2*)&b2[64 + 2*L];
    float2 b3a = *(const float2*)&b3[2*L],      b3b = *(const float2*)&b3[64 + 2*L];
    u64 i2a = pk2(b2a.x, b2a.y), i2b = pk2(b2b.x, b2b.y);
    u64 i3a = pk2(b3a.x, b3a.y), i3b = pk2(b3b.x, b3b.y);

    for (int t = blockIdx.x*NWARP + w; t < NT2; t += gridDim.x*NWARP) {
        int p0 = t*2;
        int bb = p0 >> 13;
        const uint2* Fab = g_F1ab + (size_t)bb*NN*32;
        #pragma unroll
        for (int q = 0; q < 2; q++) {
            int p = p0 + q;
            int ii = nidx[(size_t)p*KK + L];
            unsigned e01, e2d;
            {
                const float* ep = ef + (size_t)p*96 + 3*L;
                __half2 t01 = __floats2half2_rn(ep[0], ep[1]);
                __half2 t2  = __float2half2_rn(ep[2]);
                e01 = *(const unsigned*)&t01;
                e2d = *(const unsigned*)&t2;
            }
            __half2 ma = __float2half2_rn(-6.0e4f), mb = ma;
            #pragma unroll 8
            for (int k = 0; k < KK; k++) {
                int fi       = __shfl_sync(0xffffffffu, ii,  k);
                unsigned p01 = __shfl_sync(0xffffffffu, e01, k);
                unsigned p2  = __shfl_sync(0xffffffffu, e2d, k);
                __half2 he01 = *(const __half2*)&p01;
                __half2 h0 = __low2half2(he01), h1 = __high2half2(he01);
                __half2 h2v = *(const __half2*)&p2;
                uint2 v = __ldg(&Fab[(size_t)fi*32 + L]);
                __half2 ta = *(const __half2*)&v.x;
                ta = __hfma2(h0, wA[0], ta);
                ta = __hfma2(h1, wA[1], ta);
                ta = __hfma2(h2v, wA[2], ta);
                ma = __hmax2(ma, ta);
                __half2 tb = *(const __half2*)&v.y;
                tb = __hfma2(h0, wB[0], tb);
                tb = __hfma2(h1, wB[1], tb);
                tb = __hfma2(h2v, wB[2], tb);
                mb = __hmax2(mb, tb);
            }
            float2 fa = __half22float2(ma), fb = __half22float2(mb);
            fa.x = lrelu(fa.x + b1a.x);  fa.y = lrelu(fa.y + b1a.y);
            fb.x = lrelu(fb.x + b1b.x);  fb.y = lrelu(fb.y + b1b.y);
            ((float4*)stgA)[q*32 + L] = make_float4(fa.x, fa.x, fa.y, fa.y);
            ((float4*)stgB)[q*32 + L] = make_float4(fb.x, fb.x, fb.y, fb.y);
        }
        __syncwarp();
        // layer 1
        u64 ya[2], yb[2];
        ya[0] = i2a; ya[1] = i2a; yb[0] = i2b; yb[1] = i2b;
        #pragma unroll 4
        for (int jp = 0; jp < 32; jp++) {
            ulonglong2 wa = sW2a[jp*32 + L];
            ulonglong2 wb = sW2b[jp*32 + L];
            #pragma unroll
            for (int q = 0; q < 2; q++) {
                ulonglong2 aa = stgA[q*32 + jp];
                ulonglong2 ab = stgB[q*32 + jp];
                ya[q] = ffma2(aa.x, wa.x, ya[q]);
                ya[q] = ffma2(aa.y, wa.y, ya[q]);
                yb[q] = ffma2(ab.x, wb.x, yb[q]);
                yb[q] = ffma2(ab.y, wb.y, yb[q]);
            }
        }
        __syncwarp();
        #pragma unroll
        for (int q = 0; q < 2; q++) {
            float2 A = upk(ya[q]), Bv = upk(yb[q]);
            A.x = lrelu(A.x);  A.y = lrelu(A.y);
            Bv.x = lrelu(Bv.x); Bv.y = lrelu(Bv.y);
            ((float4*)stgA)[q*32 + L] = make_float4(A.x, A.x, A.y, A.y);
            ((float4*)stgB)[q*32 + L] = make_float4(Bv.x, Bv.x, Bv.y, Bv.y);
        }
        __syncwarp();
        // layer 2
        u64 oa[2], ob[2];
        oa[0] = i3a; oa[1] = i3a; ob[0] = i3b; ob[1] = i3b;
        #pragma unroll 4
        for (int jp = 0; jp < 32; jp++) {
            ulonglong2 wa = sW3a[jp*32 + L];
            ulonglong2 wb = sW3b[jp*32 + L];
            #pragma unroll
            for (int q = 0; q < 2; q++) {
                ulonglong2 aa = stgA[q*32 + jp];
                ulonglong2 ab = stgB[q*32 + jp];
                oa[q] = ffma2(aa.x, wa.x, oa[q]);
                oa[q] = ffma2(aa.y, wa.y, oa[q]);
                ob[q] = ffma2(ab.x, wb.x, ob[q]);
                ob[q] = ffma2(ab.y, wb.y, ob[q]);
            }
        }
        #pragma unroll
        for (int q = 0; q < 2; q++) {
            int p = p0 + q;
            float2 A = upk(oa[q]), Bv = upk(ob[q]);
            float z0 = sigm(A.x), z1 = sigm(A.y);
            *(float2*)&z_out[(size_t)p*64 + 2*L] = make_float2(z0, z1);
            float r0 = sigm(Bv.x), r1 = sigm(Bv.y);
            float2 hv = *(const float2*)&h[(size_t)p*64 + 2*L];
            *(float2*)&rh_out[(size_t)p*64 + 2*L] = make_float2(r0*hv.x, r1*hv.y);
        }
        __syncwarp();
    }
}

// ---------------- gate2: branch 2 -> q; out = h + z*(q-h) ----------------
__global__ void __launch_bounds__(512, 2)
gate2_kernel(const float* __restrict__ h,
    const float* __restrict__ W1, const float* __restrict__ b1,
    const float* __restrict__ W2, const float* __restrict__ b2,
    const float* __restrict__ W3, const float* __restrict__ b3,
    const int* __restrict__ nidx, const float* __restrict__ ef,
    float* __restrict__ out)
{
    extern __shared__ ulonglong2 smu[];
    // W2c [0,1024) W3c [1024,2048); staging 2048 + w*128
    int tid = threadIdx.x, w = tid>>5, L = tid&31;
    for (int i = tid; i < 2048; i += blockDim.x) {
        int arr = i >> 10, rem = i & 1023, jp = rem >> 5, l = rem & 31;
        const float* S = arr ? (W3 + 2*4096) : (W2 + 2*4096);
        ((float4*)smu)[i] = packW(S, jp, l);
    }
    __syncthreads();
    const ulonglong2* sW2c = smu;
    const ulonglong2* sW3c = smu + 1024;
    ulonglong2* stg = smu + 2048 + w*128;   // 4 pts x 32 jp

    const float* eWc = W1 + 2*131*64 + 128*64;
    __half2 wC[3];
    #pragma unroll
    for (int j = 0; j < 3; j++)
        wC[j] = __floats2half2_rn(eWc[j*64 + 2*L], eWc[j*64 + 2*L + 1]);
    float2 b1c = *(const float2*)&b1[128 + 2*L];
    float2 b2c = *(const float2*)&b2[128 + 2*L];
    float2 b3c = *(const float2*)&b3[128 + 2*L];
    u64 i2c = pk2(b2c.x, b2c.y), i3c = pk2(b3c.x, b3c.y);

    for (int t = blockIdx.x*NWARP + w; t < NT4; t += gridDim.x*NWARP) {
        int p0 = t*4;
        int bb = p0 >> 13;
        const __half2* Fc = g_F1c + (size_t)bb*NN*32;
        #pragma unroll
        for (int q = 0; q < 4; q++) {
            int p = p0 + q;
            int ii = nidx[(size_t)p*KK + L];
            unsigned e01, e2d;
            {
                const float* ep = ef + (size_t)p*96 + 3*L;
                __half2 t01 = __floats2half2_rn(ep[0], ep[1]);
                __half2 t2  = __float2half2_rn(ep[2]);
                e01 = *(const unsigned*)&t01;
                e2d = *(const unsigned*)&t2;
            }
            __half2 mc = __float2half2_rn(-6.0e4f);
            #pragma unroll 8
            for (int k = 0; k < KK; k++) {
                int fi       = __shfl_sync(0xffffffffu, ii,  k);
                unsigned p01 = __shfl_sync(0xffffffffu, e01, k);
                unsigned p2  = __shfl_sync(0xffffffffu, e2d, k);
                __half2 he01 = *(const __half2*)&p01;
                __half2 h0 = __low2half2(he01), h1 = __high2half2(he01);
                __half2 h2v = *(const __half2*)&p2;
                __half2 v = __ldg(&Fc[(size_t)fi*32 + L]);
                v = __hfma2(h0, wC[0], v);
                v = __hfma2(h1, wC[1], v);
                v = __hfma2(h2v, wC[2], v);
                mc = __hmax2(mc, v);
            }
            float2 fc = __half22float2(mc);
            fc.x = lrelu(fc.x + b1c.x);  fc.y = lrelu(fc.y + b1c.y);
            ((float4*)stg)[q*32 + L] = make_float4(fc.x, fc.x, fc.y, fc.y);
        }
        __syncwarp();
        u64 yc[4];
        #pragma unroll
        for (int q = 0; q < 4; q++) yc[q] = i2c;
        #pragma unroll 4
        for (int jp = 0; jp < 32; jp++) {
            ulonglong2 wc = sW2c[jp*32 + L];
            #pragma unroll
            for (int q = 0; q < 4; q++) {
                ulonglong2 a = stg[q*32 + jp];
                yc[q] = ffma2(a.x, wc.x, yc[q]);
                yc[q] = ffma2(a.y, wc.y, yc[q]);
            }
        }
        __syncwarp();
        #pragma unroll
        for (int q = 0; q < 4; q++) {
            float2 A = upk(yc[q]);
            A.x = lrelu(A.x);  A.y = lrelu(A.y);
            ((float4*)stg)[q*32 + L] = make_float4(A.x, A.x, A.y, A.y);
        }
        __syncwarp();
        u64 oc[4];
        #pragma unroll
        for (int q = 0; q < 4; q++) oc[q] = i3c;
        #pragma unroll 4
        for (int jp = 0; jp < 32; jp++) {
            ulonglong2 wc = sW3c[jp*32 + L];
            #pragma unroll
            for (int q = 0; q < 4; q++) {
                ulonglong2 a = stg[q*32 + jp];
                oc[q] = ffma2(a.x, wc.x, oc[q]);
                oc[q] = ffma2(a.y, wc.y, oc[q]);
            }
        }
        #pragma unroll
        for (int q = 0; q < 4; q++) {
            int p = p0 + q;
            float2 A = upk(oc[q]);
            float q0 = tanhf(A.x), q1 = tanhf(A.y);
            float2 zv = *(const float2*)&g_z[(size_t)p*64 + 2*L];
            float2 hv = *(const float2*)&h[(size_t)p*64 + 2*L];
            float o0 = hv.x + zv.x*(q0 - hv.x);
            float o1 = hv.y + zv.y*(q1 - hv.y);
            *(float2*)&out[(size_t)p*64 + 2*L] = make_float2(o0, o1);
        }
        __syncwarp();
    }
}

extern "C" void kernel_launch(void* const* d_in, const int* in_sizes, int n_in,
                              void* d_out, int out_size)
{
    const float* h   = (const float*)d_in[0];
    const float* x   = (const float*)d_in[1];
    // d_in[2] = c, unused (matches reference)
    const float* W1  = (const float*)d_in[3];
    const float* b1  = (const float*)d_in[4];
    const float* W2  = (const float*)d_in[5];
    const float* b2  = (const float*)d_in[6];
    const float* W3  = (const float*)d_in[7];
    const float* b3  = (const float*)d_in[8];
    const int*   nidx = (const int*)d_in[9];
    const float* ef  = (const float*)d_in[10];
    float* out = (float*)d_out;

    void *pF1ab, *pF1c, *pz, *prh;
    cudaGetSymbolAddress(&pF1ab, g_F1ab);
    cudaGetSymbolAddress(&pF1c,  g_F1c);
    cudaGetSymbolAddress(&pz,    g_z);
    cudaGetSymbolAddress(&prh,   g_rh);

    const int smem_lin2 = 6144 * 16;   // 96KB
    const int smem_lin1 = 4096 * 16;   // 64KB
    const int smem_g01  = 6144 * 16;   // 96KB
    const int smem_g2   = 4096 * 16;   // 64KB

    cudaFuncSetAttribute(linear2_kernel, cudaFuncAttributeMaxDynamicSharedMemorySize, smem_lin2);
    cudaFuncSetAttribute(linear1_kernel, cudaFuncAttributeMaxDynamicSharedMemorySize, smem_lin1);
    cudaFuncSetAttribute(gate01_kernel,  cudaFuncAttributeMaxDynamicSharedMemorySize, smem_g01);
    cudaFuncSetAttribute(gate2_kernel,   cudaFuncAttributeMaxDynamicSharedMemorySize, smem_g2);

    dim3 blk(512);

    // F1ab = [h|x] @ {W1a[0], W1a[1]}  (packed fp16)
    linear2_kernel<<<512, blk, smem_lin2>>>(h, x, W1, (uint2*)pF1ab);
    // z, r*h
    gate01_kernel<<<512, blk, smem_g01>>>(h, W1, b1, W2, b2, W3, b3, nidx, ef,
                                          (float*)pz, (float*)prh);
    // F1c = [r*h|x] @ W1a[2]  (fp16)
    linear1_kernel<<<512, blk, smem_lin1>>>((const float*)prh, x, W1, (__half2*)pF1c);
    // q and final output
    gate2_kernel<<<512, blk, smem_g2>>>(h, W1, b1, W2, b2, W3, b3, nidx, ef, out);
}

// round 6
// speedup vs baseline: 1.1389x; 1.1012x over previous
#include <cuda_runtime.h>
#include <cuda_fp16.h>
#include <math.h>

#define BB 4
#define NN 8192
#define KK 32
#define BN (BB*NN)
#define PT 4
#define NWARP 8
#define NTASK (BN/PT)

// scratch (device globals; no allocation)
__device__ uint2   g_F1ab[BN*32];   // per point: {a-pair, b-pair} fp16 per group L
__device__ __half2 g_F1c[BN*32];
__device__ float   g_z[BN*64];
__device__ float   g_rh[BN*64];

__device__ __forceinline__ float lrelu(float v){ return v > 0.f ? v : 0.1f*v; }
__device__ __forceinline__ float sigm(float v){ return 1.f/(1.f+expf(-v)); }

// shfl-broadcast element j of the 96 edge floats held in er0/er1/er2 (j compile-time)
#define EGET(j) __shfl_sync(0xffffffffu, ((j) < 32 ? er0 : ((j) < 64 ? er1 : er2)), (j) & 31)

// ---------------- tensor-core helpers (mma.sync HMMA) ----------------
__device__ __forceinline__ unsigned sm_u32(const void* p){
    return (unsigned)__cvta_generic_to_shared(p);
}
__device__ __forceinline__ void ldsm_x4(unsigned &r0, unsigned &r1, unsigned &r2, unsigned &r3,
                                        unsigned addr){
    asm volatile("ldmatrix.sync.aligned.m8n8.x4.shared.b16 {%0,%1,%2,%3}, [%4];"
        : "=r"(r0), "=r"(r1), "=r"(r2), "=r"(r3) : "r"(addr));
}
__device__ __forceinline__ void ldsm_x4_t(unsigned &r0, unsigned &r1, unsigned &r2, unsigned &r3,
                                          unsigned addr){
    asm volatile("ldmatrix.sync.aligned.m8n8.x4.trans.shared.b16 {%0,%1,%2,%3}, [%4];"
        : "=r"(r0), "=r"(r1), "=r"(r2), "=r"(r3) : "r"(addr));
}
__device__ __forceinline__ void mma16816(float* c,
        unsigned a0, unsigned a1, unsigned a2, unsigned a3,
        unsigned b0, unsigned b1){
    asm volatile("mma.sync.aligned.m16n8k16.row.col.f32.f16.f16.f32 "
        "{%0,%1,%2,%3}, {%4,%5,%6,%7}, {%8,%9}, {%0,%1,%2,%3};"
        : "+f"(c[0]), "+f"(c[1]), "+f"(c[2]), "+f"(c[3])
        : "r"(a0), "r"(a1), "r"(a2), "r"(a3), "r"(b0), "r"(b1));
}

// A tile: 64 pts x 128 feats, row stride 136 halfs (17x16B, conflict-free ldmatrix)
#define ASTR 136
// B (linear2): 128 x 128, stride 136; B (linear1): 128 x 64, stride 72 (9x16B)
#define B2STR 136
#define B1STR 72

// ---------------- linear2 (HMMA): F1ab = [h|x] @ {W1a[0],W1a[1]} ----------------
// out32[p*64 + (col<64 ? col : col-63)] = half2(C[col],C[col+1]) — interleaved a/b pairs
__global__ void __launch_bounds__(256)
linear2_hmma(const float* __restrict__ s0, const float* __restrict__ s1,
             const float* __restrict__ W1, unsigned* __restrict__ out32)
{
    extern __shared__ __half smh[];
    __half* A = smh;                 // 64 x ASTR
    __half* B = smh + 64*ASTR;       // 128 x B2STR
    int tid = threadIdx.x, w = tid>>5, L = tid&31;
    int wm = w >> 1, wn = w & 1;     // 4 m-warps x 2 n-warps

    const float* Wa = W1;
    const float* Wb = W1 + 131*64;
    for (int i = tid; i < 128*64; i += 256) {
        int k = i >> 6, n = i & 63;
        B[k*B2STR + n]      = __float2half_rn(Wa[k*64 + n]);
        B[k*B2STR + 64 + n] = __float2half_rn(Wb[k*64 + n]);
    }
    __syncthreads();

    int r = L >> 2, cq = (L & 3) * 2;
    for (int tile = blockIdx.x; tile < BN/64; tile += gridDim.x) {
        int pt0 = tile * 64;
        // stage A (fp32 -> fp16), 64 pts x 64 half2 columns
        for (int i = tid; i < 64*64; i += 256) {
            int p = i >> 6, c2 = i & 63;
            float2 v = (c2 < 32) ? *(const float2*)&s0[(size_t)(pt0+p)*64 + 2*c2]
                                 : *(const float2*)&s1[(size_t)(pt0+p)*64 + 2*(c2-32)];
            *(__half2*)&A[p*ASTR + 2*c2] = __floats2half2_rn(v.x, v.y);
        }
        __syncthreads();

        float C[8][4];
        #pragma unroll
        for (int i = 0; i < 8; i++)
            #pragma unroll
            for (int j = 0; j < 4; j++) C[i][j] = 0.f;

        #pragma unroll
        for (int ks = 0; ks < 8; ks++) {
            int k0 = ks * 16;
            unsigned a0,a1,a2,a3;
            ldsm_x4(a0,a1,a2,a3, sm_u32(&A[(wm*16 + (L&15))*ASTR + k0 + (L>>4)*8]));
            #pragma unroll
            for (int nt = 0; nt < 4; nt++) {
                unsigned b0,b1,b2,b3;
                ldsm_x4_t(b0,b1,b2,b3,
                    sm_u32(&B[(k0 + (L&15))*B2STR + wn*64 + nt*16 + (L>>4)*8]));
                mma16816(C[2*nt],   a0,a1,a2,a3, b0,b1);
                mma16816(C[2*nt+1], a0,a1,a2,a3, b2,b3);
            }
        }
        // epilogue: pack adjacent-col pairs as half2, scatter into interleaved layout
        #pragma unroll
        for (int nt8 = 0; nt8 < 8; nt8++) {
            int col = wn*64 + nt8*8 + cq;
            int oidx = (col < 64) ? col : (col - 63);
            int p = pt0 + wm*16 + r;
            __half2 lo = __floats2half2_rn(C[nt8][0], C[nt8][1]);
            __half2 hi = __floats2half2_rn(C[nt8][2], C[nt8][3]);
            out32[(size_t)p*64 + oidx]     = *(const unsigned*)&lo;
            out32[(size_t)(p+8)*64 + oidx] = *(const unsigned*)&hi;
        }
        __syncthreads();
    }
}

// ---------------- linear1 (HMMA): F1c = [rh|x] @ W1a[2] ----------------
__global__ void __launch_bounds__(256)
linear1_hmma(const float* __restrict__ s0, const float* __restrict__ s1,
             const float* __restrict__ W1, unsigned* __restrict__ out32)
{
    extern __shared__ __half smh[];
    __half* A = smh;                 // 64 x ASTR
    __half* B = smh + 64*ASTR;       // 128 x B1STR
    int tid = threadIdx.x, w = tid>>5, L = tid&31;
    int wm = w >> 1, wn = w & 1;

    const float* Wc = W1 + 2*131*64;
    for (int i = tid; i < 128*64; i += 256) {
        int k = i >> 6, n = i & 63;
        B[k*B1STR + n] = __float2half_rn(Wc[k*64 + n]);
    }
    __syncthreads();

    int r = L >> 2, cq = (L & 3) * 2;
    for (int tile = blockIdx.x; tile < BN/64; tile += gridDim.x) {
        int pt0 = tile * 64;
        for (int i = tid; i < 64*64; i += 256) {
            int p = i >> 6, c2 = i & 63;
            float2 v = (c2 < 32) ? *(const float2*)&s0[(size_t)(pt0+p)*64 + 2*c2]
                                 : *(const float2*)&s1[(size_t)(pt0+p)*64 + 2*(c2-32)];
            *(__half2*)&A[p*ASTR + 2*c2] = __floats2half2_rn(v.x, v.y);
        }
        __syncthreads();

        float C[4][4];
        #pragma unroll
        for (int i = 0; i < 4; i++)
            #pragma unroll
            for (int j = 0; j < 4; j++) C[i][j] = 0.f;

        #pragma unroll
        for (int ks = 0; ks < 8; ks++) {
            int k0 = ks * 16;
            unsigned a0,a1,a2,a3;
            ldsm_x4(a0,a1,a2,a3, sm_u32(&A[(wm*16 + (L&15))*ASTR + k0 + (L>>4)*8]));
            #pragma unroll
            for (int nt = 0; nt < 2; nt++) {
                unsigned b0,b1,b2,b3;
                ldsm_x4_t(b0,b1,b2,b3,
                    sm_u32(&B[(k0 + (L&15))*B1STR + wn*32 + nt*16 + (L>>4)*8]));
                mma16816(C[2*nt],   a0,a1,a2,a3, b0,b1);
                mma16816(C[2*nt+1], a0,a1,a2,a3, b2,b3);
            }
        }
        #pragma unroll
        for (int nt8 = 0; nt8 < 4; nt8++) {
            int col = wn*32 + nt8*8 + cq;
            int p = pt0 + wm*16 + r;
            __half2 lo = __floats2half2_rn(C[nt8][0], C[nt8][1]);
            __half2 hi = __floats2half2_rn(C[nt8][2], C[nt8][3]);
            out32[(size_t)p*32 + (col>>1)]     = *(const unsigned*)&lo;
            out32[(size_t)(p+8)*32 + (col>>1)] = *(const unsigned*)&hi;
        }
        __syncthreads();
    }
}

// ---------------- gate01: branches 0+1 -> z, r*h  (R2-proven version) ----------------
__global__ void gate01_kernel(const float* __restrict__ h,
    const float* __restrict__ W1, const float* __restrict__ b1,
    const float* __restrict__ W2, const float* __restrict__ b2,
    const float* __restrict__ W3, const float* __restrict__ b3,
    const int* __restrict__ nidx, const float* __restrict__ ef,
    float* __restrict__ z_out, float* __restrict__ rh_out)
{
    extern __shared__ float sm[];
    float* sW2 = sm;                // 64*128 packed {a0,a1,b0,b1}
    float* sW3 = sm + 8192;         // 64*128 packed
    float* sStg = sm + 16384;       // NWARP * 512
    int tid = threadIdx.x, w = tid>>5, L = tid&31;
    for (int i = tid; i < 2048; i += blockDim.x) {
        int j = i >> 5, l = i & 31;
        float4 w2, w3;
        w2.x = W2[j*64 + 2*l];        w2.y = W2[j*64 + 2*l + 1];
        w2.z = W2[4096 + j*64 + 2*l]; w2.w = W2[4096 + j*64 + 2*l + 1];
        ((float4*)sW2)[i] = w2;
        w3.x = W3[j*64 + 2*l];        w3.y = W3[j*64 + 2*l + 1];
        w3.z = W3[4096 + j*64 + 2*l]; w3.w = W3[4096 + j*64 + 2*l + 1];
        ((float4*)sW3)[i] = w3;
    }
    __syncthreads();

    const float* eWa = W1 + 128*64;                // branch 0 edge rows
    const float* eWb = W1 + 131*64 + 128*64;       // branch 1 edge rows
    float2 wEa[3], wEb[3];
    #pragma unroll
    for (int j = 0; j < 3; j++) {
        wEa[j] = *(const float2*)&eWa[j*64 + 2*L];
        wEb[j] = *(const float2*)&eWb[j*64 + 2*L];
    }
    float2 b1a = *(const float2*)&b1[2*L],      b1b = *(const float2*)&b1[64 + 2*L];
    float2 b2a = *(const float2*)&b2[2*L],      b2b = *(const float2*)&b2[64 + 2*L];
    float2 b3a = *(const float2*)&b3[2*L],      b3b = *(const float2*)&b3[64 + 2*L];

    float* st = sStg + w*512;   // [0:256) branch a, [256:512) branch b
    for (int t = blockIdx.x*NWARP + w; t < NTASK; t += gridDim.x*NWARP) {
        int p0 = t*PT;
        int bb = p0 >> 13;
        const uint2* Fab = g_F1ab + (size_t)bb*NN*32;
        #pragma unroll
        for (int q = 0; q < PT; q++) {
            int p = p0 + q;
            int ii = nidx[(size_t)p*KK + L];
            float er0 = ef[(size_t)p*96 + L];
            float er1 = ef[(size_t)p*96 + 32 + L];
            float er2 = ef[(size_t)p*96 + 64 + L];
            __half2 ma = __float2half2_rn(-6.0e4f);
            __half2 mb = ma;
            #pragma unroll
            for (int k = 0; k < KK; k++) {
                int fi = __shfl_sync(0xffffffffu, ii, k);
                uint2 v = __ldg(&Fab[(size_t)fi*32 + L]);
                float e0 = EGET(3*k), e1 = EGET(3*k+1), e2 = EGET(3*k+2);
                float ea0 = fmaf(e2, wEa[2].x, fmaf(e1, wEa[1].x, e0*wEa[0].x));
                float ea1 = fmaf(e2, wEa[2].y, fmaf(e1, wEa[1].y, e0*wEa[0].y));
                float eb0 = fmaf(e2, wEb[2].x, fmaf(e1, wEb[1].x, e0*wEb[0].x));
                float eb1 = fmaf(e2, wEb[2].y, fmaf(e1, wEb[1].y, e0*wEb[0].y));
                __half2 ea = __floats2half2_rn(ea0, ea1);
                __half2 eb = __floats2half2_rn(eb0, eb1);
                ma = __hmax2(ma, __hadd2(*(const __half2*)&v.x, ea));
                mb = __hmax2(mb, __hadd2(*(const __half2*)&v.y, eb));
            }
            float2 fa = __half22float2(ma);
            float2 fb = __half22float2(mb);
            fa.x = lrelu(fa.x + b1a.x);  fa.y = lrelu(fa.y + b1a.y);
            fb.x = lrelu(fb.x + b1b.x);  fb.y = lrelu(fb.y + b1b.y);
            *(float2*)&st[q*64 + 2*L]       = fa;
            *(float2*)&st[256 + q*64 + 2*L] = fb;
        }
        __syncwarp();
        // layer 1
        float ya[PT][2], yb[PT][2];
        #pragma unroll
        for (int q = 0; q < PT; q++) {
            ya[q][0] = b2a.x; ya[q][1] = b2a.y;
            yb[q][0] = b2b.x; yb[q][1] = b2b.y;
        }
        #pragma unroll 8
        for (int j = 0; j < 64; j++) {
            float4 wv = ((const float4*)sW2)[j*32 + L];
            #pragma unroll
            for (int q = 0; q < PT; q++) {
                float pa = st[q*64 + j];
                float pb = st[256 + q*64 + j];
                ya[q][0] += pa*wv.x; ya[q][1] += pa*wv.y;
                yb[q][0] += pb*wv.z; yb[q][1] += pb*wv.w;
            }
        }
        __syncwarp();
        #pragma unroll
        for (int q = 0; q < PT; q++) {
            *(float2*)&st[q*64 + 2*L]       = make_float2(lrelu(ya[q][0]), lrelu(ya[q][1]));
            *(float2*)&st[256 + q*64 + 2*L] = make_float2(lrelu(yb[q][0]), lrelu(yb[q][1]));
        }
        __syncwarp();
        // layer 2
        float oa[PT][2], ob[PT][2];
        #pragma unroll
        for (int q = 0; q < PT; q++) {
            oa[q][0] = b3a.x; oa[q][1] = b3a.y;
            ob[q][0] = b3b.x; ob[q][1] = b3b.y;
        }
        #pragma unroll 8
        for (int j = 0; j < 64; j++) {
            float4 wv = ((const float4*)sW3)[j*32 + L];
            #pragma unroll
            for (int q = 0; q < PT; q++) {
                float y_a = st[q*64 + j];
                float y_b = st[256 + q*64 + j];
                oa[q][0] += y_a*wv.x; oa[q][1] += y_a*wv.y;
                ob[q][0] += y_b*wv.z; ob[q][1] += y_b*wv.w;
            }
        }
        #pragma unroll
        for (int q = 0; q < PT; q++) {
            int p = p0 + q;
            float z0 = sigm(oa[q][0]), z1 = sigm(oa[q][1]);
            *(float2*)&z_out[(size_t)p*64 + 2*L] = make_float2(z0, z1);
            float r0 = sigm(ob[q][0]), r1 = sigm(ob[q][1]);
            float2 hv = *(const float2*)&h[(size_t)p*64 + 2*L];
            *(float2*)&rh_out[(size_t)p*64 + 2*L] = make_float2(r0*hv.x, r1*hv.y);
        }
        __syncwarp();
    }
}

// ---------------- gate2: branch 2 -> q; out = h + z*(q-h)  (R2-proven version) ----------------
__global__ void gate2_kernel(const float* __restrict__ h,
    const float* __restrict__ W1, const float* __restrict__ b1,
    const float* __restrict__ W2, const float* __restrict__ b2,
    const float* __restrict__ W3, const float* __restrict__ b3,
    const int* __restrict__ nidx, const float* __restrict__ ef,
    float* __restrict__ out)
{
    extern __shared__ float sm[];
    float* sW2 = sm;                // 4096
    float* sW3 = sm + 4096;         // 4096
    float* sStg = sm + 8192;        // NWARP * 256
    int tid = threadIdx.x, w = tid>>5, L = tid&31;
    for (int i = tid; i < 4096; i += blockDim.x) {
        sW2[i] = W2[2*4096 + i];
        sW3[i] = W3[2*4096 + i];
    }
    __syncthreads();

    const float* eWc = W1 + 2*131*64 + 128*64;
    float2 wEc[3];
    #pragma unroll
    for (int j = 0; j < 3; j++) wEc[j] = *(const float2*)&eWc[j*64 + 2*L];
    float2 b1c = *(const float2*)&b1[128 + 2*L];
    float2 b2c = *(const float2*)&b2[128 + 2*L];
    float2 b3c = *(const float2*)&b3[128 + 2*L];

    float* st = sStg + w*256;
    for (int t = blockIdx.x*NWARP + w; t < NTASK; t += gridDim.x*NWARP) {
        int p0 = t*PT;
        int bb = p0 >> 13;
        const __half2* Fc = g_F1c + (size_t)bb*NN*32;
        #pragma unroll
        for (int q = 0; q < PT; q++) {
            int p = p0 + q;
            int ii = nidx[(size_t)p*KK + L];
            float er0 = ef[(size_t)p*96 + L];
            float er1 = ef[(size_t)p*96 + 32 + L];
            float er2 = ef[(size_t)p*96 + 64 + L];
            __half2 mc = __float2half2_rn(-6.0e4f);
            #pragma unroll
            for (int k = 0; k < KK; k++) {
                int fi = __shfl_sync(0xffffffffu, ii, k);
                __half2 v = __ldg(&Fc[(size_t)fi*32 + L]);
                float e0 = EGET(3*k), e1 = EGET(3*k+1), e2 = EGET(3*k+2);
                float ec0 = fmaf(e2, wEc[2].x, fmaf(e1, wEc[1].x, e0*wEc[0].x));
                float ec1 = fmaf(e2, wEc[2].y, fmaf(e1, wEc[1].y, e0*wEc[0].y));
                __half2 ec = __floats2half2_rn(ec0, ec1);
                mc = __hmax2(mc, __hadd2(v, ec));
            }
            float2 fc = __half22float2(mc);
            fc.x = lrelu(fc.x + b1c.x);  fc.y = lrelu(fc.y + b1c.y);
            *(float2*)&st[q*64 + 2*L] = fc;
        }
        __syncwarp();
        float yc[PT][2];
        #pragma unroll
        for (int q = 0; q < PT; q++) { yc[q][0] = b2c.x; yc[q][1] = b2c.y; }
        #pragma unroll 8
        for (int j = 0; j < 64; j++) {
            float2 wv = *(const float2*)&sW2[j*64 + 2*L];
            #pragma unroll
            for (int q = 0; q < PT; q++) {
                float pv = st[q*64 + j];
                yc[q][0] += pv*wv.x; yc[q][1] += pv*wv.y;
            }
        }
        __syncwarp();
        #pragma unroll
        for (int q = 0; q < PT; q++)
            *(float2*)&st[q*64 + 2*L] = make_float2(lrelu(yc[q][0]), lrelu(yc[q][1]));
        __syncwarp();
        float oc[PT][2];
        #pragma unroll
        for (int q = 0; q < PT; q++) { oc[q][0] = b3c.x; oc[q][1] = b3c.y; }
        #pragma unroll 8
        for (int j = 0; j < 64; j++) {
            float2 wv = *(const float2*)&sW3[j*64 + 2*L];
            #pragma unroll
            for (int q = 0; q < PT; q++) {
                float yv = st[q*64 + j];
                oc[q][0] += yv*wv.x; oc[q][1] += yv*wv.y;
            }
        }
        #pragma unroll
        for (int q = 0; q < PT; q++) {
            int p = p0 + q;
            float q0 = tanhf(oc[q][0]), q1 = tanhf(oc[q][1]);
            float2 zv = *(const float2*)&g_z[(size_t)p*64 + 2*L];
            float2 hv = *(const float2*)&h[(size_t)p*64 + 2*L];
            float o0 = hv.x + zv.x*(q0 - hv.x);
            float o1 = hv.y + zv.y*(q1 - hv.y);
            *(float2*)&out[(size_t)p*64 + 2*L] = make_float2(o0, o1);
        }
        __syncwarp();
    }
}

extern "C" void kernel_launch(void* const* d_in, const int* in_sizes, int n_in,
                              void* d_out, int out_size)
{
    const float* h   = (const float*)d_in[0];
    const float* x   = (const float*)d_in[1];
    // d_in[2] = c, unused (matches reference)
    const float* W1  = (const float*)d_in[3];
    const float* b1  = (const float*)d_in[4];
    const float* W2  = (const float*)d_in[5];
    const float* b2  = (const float*)d_in[6];
    const float* W3  = (const float*)d_in[7];
    const float* b3  = (const float*)d_in[8];
    const int*   nidx = (const int*)d_in[9];
    const float* ef  = (const float*)d_in[10];
    float* out = (float*)d_out;

    void *pF1ab, *pF1c, *pz, *prh;
    cudaGetSymbolAddress(&pF1ab, g_F1ab);
    cudaGetSymbolAddress(&pF1c,  g_F1c);
    cudaGetSymbolAddress(&pz,    g_z);
    cudaGetSymbolAddress(&prh,   g_rh);

    const int smem_l2h = (64*ASTR + 128*B2STR) * 2;   // 52224 B
    const int smem_l1h = (64*ASTR + 128*B1STR) * 2;   // 35840 B
    const int smem_g01 = (16384 + NWARP*512) * 4;     // 81920 B
    const int smem_g2  = (8192 + NWARP*256) * 4;      // 40960 B

    cudaFuncSetAttribute(linear2_hmma, cudaFuncAttributeMaxDynamicSharedMemorySize, smem_l2h);
    cudaFuncSetAttribute(linear1_hmma, cudaFuncAttributeMaxDynamicSharedMemorySize, smem_l1h);
    cudaFuncSetAttribute(gate01_kernel, cudaFuncAttributeMaxDynamicSharedMemorySize, smem_g01);
    cudaFuncSetAttribute(gate2_kernel,  cudaFuncAttributeMaxDynamicSharedMemorySize, smem_g2);

    dim3 blk(256);

    // F1ab = [h|x] @ {W1a[0], W1a[1]}  (HMMA, packed fp16 out)
    linear2_hmma<<<296, blk, smem_l2h>>>(h, x, W1, (unsigned*)pF1ab);
    // z, r*h
    gate01_kernel<<<296, blk, smem_g01>>>(h, W1, b1, W2, b2, W3, b3, nidx, ef,
                                          (float*)pz, (float*)prh);
    // F1c = [r*h|x] @ W1a[2]  (HMMA, fp16 out)
    linear1_hmma<<<296, blk, smem_l1h>>>((const float*)prh, x, W1, (unsigned*)pF1c);
    // q and final output
    gate2_kernel<<<592, blk, smem_g2>>>(h, W1, b1, W2, b2, W3, b3, nidx, ef, out);
}

// round 11
// speedup vs baseline: 1.7930x; 1.5743x over previous
#include <cuda_runtime.h>
#include <cuda_fp16.h>
#include <math.h>

#define BB 4
#define NN 8192
#define KK 32
#define BN (BB*NN)
#define PT 4
#define NWARP 8
#define NTASK (BN/PT)

// scratch (device globals; no allocation)
__device__ uint2   g_F1ab[BN*32];   // per point: {a-pair, b-pair} fp16 per group L
__device__ __half2 g_F1c[BN*32];
__device__ float   g_z[BN*64];
__device__ float   g_rh[BN*64];

__device__ __forceinline__ float lrelu(float v){ return v > 0.f ? v : 0.1f*v; }
__device__ __forceinline__ float sigm(float v){ return 1.f/(1.f+expf(-v)); }

// ---------------- tensor-core helpers (mma.sync HMMA) ----------------
__device__ __forceinline__ unsigned sm_u32(const void* p){
    return (unsigned)__cvta_generic_to_shared(p);
}
__device__ __forceinline__ void ldsm_x4(unsigned &r0, unsigned &r1, unsigned &r2, unsigned &r3,
                                        unsigned addr){
    asm volatile("ldmatrix.sync.aligned.m8n8.x4.shared.b16 {%0,%1,%2,%3}, [%4];"
        : "=r"(r0), "=r"(r1), "=r"(r2), "=r"(r3) : "r"(addr));
}
__device__ __forceinline__ void ldsm_x4_t(unsigned &r0, unsigned &r1, unsigned &r2, unsigned &r3,
                                          unsigned addr){
    asm volatile("ldmatrix.sync.aligned.m8n8.x4.trans.shared.b16 {%0,%1,%2,%3}, [%4];"
        : "=r"(r0), "=r"(r1), "=r"(r2), "=r"(r3) : "r"(addr));
}
__device__ __forceinline__ void mma16816(float* c,
        unsigned a0, unsigned a1, unsigned a2, unsigned a3,
        unsigned b0, unsigned b1){
    asm volatile("mma.sync.aligned.m16n8k16.row.col.f32.f16.f16.f32 "
        "{%0,%1,%2,%3}, {%4,%5,%6,%7}, {%8,%9}, {%0,%1,%2,%3};"
        : "+f"(c[0]), "+f"(c[1]), "+f"(c[2]), "+f"(c[3])
        : "r"(a0), "r"(a1), "r"(a2), "r"(a3), "r"(b0), "r"(b1));
}

#define ASTR 136
#define B2STR 136
#define B1STR 72

// ---------------- linear2 (HMMA): F1ab = [h|x] @ {W1a[0],W1a[1]} ----------------
__global__ void __launch_bounds__(256)
linear2_hmma(const float* __restrict__ s0, const float* __restrict__ s1,
             const float* __restrict__ W1, unsigned* __restrict__ out32)
{
    extern __shared__ __half smh[];
    __half* A = smh;                 // 64 x ASTR
    __half* B = smh + 64*ASTR;       // 128 x B2STR
    int tid = threadIdx.x, w = tid>>5, L = tid&31;
    int wm = w >> 1, wn = w & 1;     // 4 m-warps x 2 n-warps

    const float* Wa = W1;
    const float* Wb = W1 + 131*64;
    for (int i = tid; i < 128*64; i += 256) {
        int k = i >> 6, n = i & 63;
        B[k*B2STR + n]      = __float2half_rn(Wa[k*64 + n]);
        B[k*B2STR + 64 + n] = __float2half_rn(Wb[k*64 + n]);
    }
    __syncthreads();

    int r = L >> 2, cq = (L & 3) * 2;
    for (int tile = blockIdx.x; tile < BN/64; tile += gridDim.x) {
        int pt0 = tile * 64;
        for (int i = tid; i < 64*64; i += 256) {
            int p = i >> 6, c2 = i & 63;
            float2 v = (c2 < 32) ? *(const float2*)&s0[(size_t)(pt0+p)*64 + 2*c2]
                                 : *(const float2*)&s1[(size_t)(pt0+p)*64 + 2*(c2-32)];
            *(__half2*)&A[p*ASTR + 2*c2] = __floats2half2_rn(v.x, v.y);
        }
        __syncthreads();

        float C[8][4];
        #pragma unroll
        for (int i = 0; i < 8; i++)
            #pragma unroll
            for (int j = 0; j < 4; j++) C[i][j] = 0.f;

        #pragma unroll
        for (int ks = 0; ks < 8; ks++) {
            int k0 = ks * 16;
            unsigned a0,a1,a2,a3;
            ldsm_x4(a0,a1,a2,a3, sm_u32(&A[(wm*16 + (L&15))*ASTR + k0 + (L>>4)*8]));
            #pragma unroll
            for (int nt = 0; nt < 4; nt++) {
                unsigned b0,b1,b2,b3;
                ldsm_x4_t(b0,b1,b2,b3,
                    sm_u32(&B[(k0 + (L&15))*B2STR + wn*64 + nt*16 + (L>>4)*8]));
                mma16816(C[2*nt],   a0,a1,a2,a3, b0,b1);
                mma16816(C[2*nt+1], a0,a1,a2,a3, b2,b3);
            }
        }
        #pragma unroll
        for (int nt8 = 0; nt8 < 8; nt8++) {
            int col = wn*64 + nt8*8 + cq;
            int oidx = (col < 64) ? col : (col - 63);
            int p = pt0 + wm*16 + r;
            __half2 lo = __floats2half2_rn(C[nt8][0], C[nt8][1]);
            __half2 hi = __floats2half2_rn(C[nt8][2], C[nt8][3]);
            out32[(size_t)p*64 + oidx]     = *(const unsigned*)&lo;
            out32[(size_t)(p+8)*64 + oidx] = *(const unsigned*)&hi;
        }
        __syncthreads();
    }
}

// ---------------- linear1 (HMMA): F1c = [rh|x] @ W1a[2] ----------------
__global__ void __launch_bounds__(256)
linear1_hmma(const float* __restrict__ s0, const float* __restrict__ s1,
             const float* __restrict__ W1, unsigned* __restrict__ out32)
{
    extern __shared__ __half smh[];
    __half* A = smh;
    __half* B = smh + 64*ASTR;
    int tid = threadIdx.x, w = tid>>5, L = tid&31;
    int wm = w >> 1, wn = w & 1;

    const float* Wc = W1 + 2*131*64;
    for (int i = tid; i < 128*64; i += 256) {
        int k = i >> 6, n = i & 63;
        B[k*B1STR + n] = __float2half_rn(Wc[k*64 + n]);
    }
    __syncthreads();

    int r = L >> 2, cq = (L & 3) * 2;
    for (int tile = blockIdx.x; tile < BN/64; tile += gridDim.x) {
        int pt0 = tile * 64;
        for (int i = tid; i < 64*64; i += 256) {
            int p = i >> 6, c2 = i & 63;
            float2 v = (c2 < 32) ? *(const float2*)&s0[(size_t)(pt0+p)*64 + 2*c2]
                                 : *(const float2*)&s1[(size_t)(pt0+p)*64 + 2*(c2-32)];
            *(__half2*)&A[p*ASTR + 2*c2] = __floats2half2_rn(v.x, v.y);
        }
        __syncthreads();

        float C[4][4];
        #pragma unroll
        for (int i = 0; i < 4; i++)
            #pragma unroll
            for (int j = 0; j < 4; j++) C[i][j] = 0.f;

        #pragma unroll
        for (int ks = 0; ks < 8; ks++) {
            int k0 = ks * 16;
            unsigned a0,a1,a2,a3;
            ldsm_x4(a0,a1,a2,a3, sm_u32(&A[(wm*16 + (L&15))*ASTR + k0 + (L>>4)*8]));
            #pragma unroll
            for (int nt = 0; nt < 2; nt++) {
                unsigned b0,b1,b2,b3;
                ldsm_x4_t(b0,b1,b2,b3,
                    sm_u32(&B[(k0 + (L&15))*B1STR + wn*32 + nt*16 + (L>>4)*8]));
                mma16816(C[2*nt],   a0,a1,a2,a3, b0,b1);
                mma16816(C[2*nt+1], a0,a1,a2,a3, b2,b3);
            }
        }
        #pragma unroll
        for (int nt8 = 0; nt8 < 4; nt8++) {
            int col = wn*32 + nt8*8 + cq;
            int p = pt0 + wm*16 + r;
            __half2 lo = __floats2half2_rn(C[nt8][0], C[nt8][1]);
            __half2 hi = __floats2half2_rn(C[nt8][2], C[nt8][3]);
            out32[(size_t)p*32 + (col>>1)]     = *(const unsigned*)&lo;
            out32[(size_t)(p+8)*32 + (col>>1)] = *(const unsigned*)&hi;
        }
        __syncthreads();
    }
}

// ---------------- gate01: branches 0+1 -> z, r*h (SMEM-meta gather) ----------------
__global__ void gate01_kernel(const float* __restrict__ h,
    const float* __restrict__ W1, const float* __restrict__ b1,
    const float* __restrict__ W2, const float* __restrict__ b2,
    const float* __restrict__ W3, const float* __restrict__ b3,
    const int* __restrict__ nidx, const float* __restrict__ ef,
    float* __restrict__ z_out, float* __restrict__ rh_out)
{
    extern __shared__ float sm[];
    float* sW2 = sm;                 // 64*128 packed {a0,a1,b0,b1}
    float* sW3 = sm + 8192;
    float* sStg = sm + 16384;        // NWARP * 512 floats
    uint2* sMeta = (uint2*)(sm + 16384 + NWARP*512);  // NWARP * 32 uint2
    int tid = threadIdx.x, w = tid>>5, L = tid&31;
    for (int i = tid; i < 2048; i += blockDim.x) {
        int j = i >> 5, l = i & 31;
        float4 w2, w3;
        w2.x = W2[j*64 + 2*l];        w2.y = W2[j*64 + 2*l + 1];
        w2.z = W2[4096 + j*64 + 2*l]; w2.w = W2[4096 + j*64 + 2*l + 1];
        ((float4*)sW2)[i] = w2;
        w3.x = W3[j*64 + 2*l];        w3.y = W3[j*64 + 2*l + 1];
        w3.z = W3[4096 + j*64 + 2*l]; w3.w = W3[4096 + j*64 + 2*l + 1];
        ((float4*)sW3)[i] = w3;
    }
    __syncthreads();

    const float* eWa = W1 + 128*64;
    const float* eWb = W1 + 131*64 + 128*64;
    __half2 wA[3], wB[3];
    #pragma unroll
    for (int j = 0; j < 3; j++) {
        wA[j] = __floats2half2_rn(eWa[j*64 + 2*L], eWa[j*64 + 2*L + 1]);
        wB[j] = __floats2half2_rn(eWb[j*64 + 2*L], eWb[j*64 + 2*L + 1]);
    }
    float2 b1a = *(const float2*)&b1[2*L],      b1b = *(const float2*)&b1[64 + 2*L];
    float2 b2a = *(const float2*)&b2[2*L],      b2b = *(const float2*)&b2[64 + 2*L];
    float2 b3a = *(const float2*)&b3[2*L],      b3b = *(const float2*)&b3[64 + 2*L];

    float* st = sStg + w*512;
    uint2* mt = sMeta + w*32;
    for (int t = blockIdx.x*NWARP + w; t < NTASK; t += gridDim.x*NWARP) {
        int p0 = t*PT;
        int bb = p0 >> 13;
        const uint2* Fab = g_F1ab + (size_t)bb*NN*32;
        #pragma unroll
        for (int q = 0; q < PT; q++) {
            int p = p0 + q;
            {
                int fi = nidx[(size_t)p*KK + L];
                const float* ep = ef + (size_t)p*96 + 3*L;
                __half2 e01 = __floats2half2_rn(ep[0], ep[1]);
                unsigned e2b = (unsigned)__half_as_ushort(__float2half_rn(ep[2]));
                mt[L] = make_uint2((unsigned)fi | (e2b << 16), *(const unsigned*)&e01);
            }
            __syncwarp();
            __half2 ma = __float2half2_rn(-6.0e4f), mb = ma;
            #pragma unroll 8
            for (int k = 0; k < KK; k++) {
                uint2 m = mt[k];
                int fi = (int)(m.x & 0xFFFFu);
                __half2 h2v = __half2half2(__ushort_as_half((unsigned short)(m.x >> 16)));
                __half2 e01 = *(const __half2*)&m.y;
                __half2 h0 = __low2half2(e01), h1 = __high2half2(e01);
                uint2 v = __ldg(&Fab[(size_t)fi*32 + L]);
                __half2 ta = *(const __half2*)&v.x;
                ta = __hfma2(h0, wA[0], ta);
                ta = __hfma2(h1, wA[1], ta);
                ta = __hfma2(h2v, wA[2], ta);
                ma = __hmax2(ma, ta);
                __half2 tb = *(const __half2*)&v.y;
                tb = __hfma2(h0, wB[0], tb);
                tb = __hfma2(h1, wB[1], tb);
                tb = __hfma2(h2v, wB[2], tb);
                mb = __hmax2(mb, tb);
            }
            __syncwarp();
            float2 fa = __half22float2(ma), fb = __half22float2(mb);
            fa.x = lrelu(fa.x + b1a.x);  fa.y = lrelu(fa.y + b1a.y);
            fb.x = lrelu(fb.x + b1b.x);  fb.y = lrelu(fb.y + b1b.y);
            *(float2*)&st[q*64 + 2*L]       = fa;
            *(float2*)&st[256 + q*64 + 2*L] = fb;
        }
        __syncwarp();
        // layer 1
        float ya[PT][2], yb[PT][2];
        #pragma unroll
        for (int q = 0; q < PT; q++) {
            ya[q][0] = b2a.x; ya[q][1] = b2a.y;
            yb[q][0] = b2b.x; yb[q][1] = b2b.y;
        }
        #pragma unroll 8
        for (int j = 0; j < 64; j++) {
            float4 wv = ((const float4*)sW2)[j*32 + L];
            #pragma unroll
            for (int q = 0; q < PT; q++) {
                float pa = st[q*64 + j];
                float pb = st[256 + q*64 + j];
                ya[q][0] += pa*wv.x; ya[q][1] += pa*wv.y;
                yb[q][0] += pb*wv.z; yb[q][1] += pb*wv.w;
            }
        }
        __syncwarp();
        #pragma unroll
        for (int q = 0; q < PT; q++) {
            *(float2*)&st[q*64 + 2*L]       = make_float2(lrelu(ya[q][0]), lrelu(ya[q][1]));
            *(float2*)&st[256 + q*64 + 2*L] = make_float2(lrelu(yb[q][0]), lrelu(yb[q][1]));
        }
        __syncwarp();
        // layer 2
        float oa[PT][2], ob[PT][2];
        #pragma unroll
        for (int q = 0; q < PT; q++) {
            oa[q][0] = b3a.x; oa[q][1] = b3a.y;
            ob[q][0] = b3b.x; ob[q][1] = b3b.y;
        }
        #pragma unroll 8
        for (int j = 0; j < 64; j++) {
            float4 wv = ((const float4*)sW3)[j*32 + L];
            #pragma unroll
            for (int q = 0; q < PT; q++) {
                float y_a = st[q*64 + j];
                float y_b = st[256 + q*64 + j];
                oa[q][0] += y_a*wv.x; oa[q][1] += y_a*wv.y;
                ob[q][0] += y_b*wv.z; ob[q][1] += y_b*wv.w;
            }
        }
        #pragma unroll
        for (int q = 0; q < PT; q++) {
            int p = p0 + q;
            float z0 = sigm(oa[q][0]), z1 = sigm(oa[q][1]);
            *(float2*)&z_out[(size_t)p*64 + 2*L] = make_float2(z0, z1);
            float r0 = sigm(ob[q][0]), r1 = sigm(ob[q][1]);
            float2 hv = *(const float2*)&h[(size_t)p*64 + 2*L];
            *(float2*)&rh_out[(size_t)p*64 + 2*L] = make_float2(r0*hv.x, r1*hv.y);
        }
        __syncwarp();
    }
}

// ---------------- gate2: branch 2 -> q; out = h + z*(q-h) (SMEM-meta gather) ----------------
__global__ void gate2_kernel(const float* __restrict__ h,
    const float* __restrict__ W1, const float* __restrict__ b1,
    const float* __restrict__ W2, const float* __restrict__ b2,
    const float* __restrict__ W3, const float* __restrict__ b3,
    const int* __restrict__ nidx, const float* __restrict__ ef,
    float* __restrict__ out)
{
    extern __shared__ float sm[];
    float* sW2 = sm;
    float* sW3 = sm + 4096;
    float* sStg = sm + 8192;         // NWARP * 256 floats
    uint2* sMeta = (uint2*)(sm + 8192 + NWARP*256);
    int tid = threadIdx.x, w = tid>>5, L = tid&31;
    for (int i = tid; i < 4096; i += blockDim.x) {
        sW2[i] = W2[2*4096 + i];
        sW3[i] = W3[2*4096 + i];
    }
    __syncthreads();

    const float* eWc = W1 + 2*131*64 + 128*64;
    __half2 wC[3];
    #pragma unroll
    for (int j = 0; j < 3; j++)
        wC[j] = __floats2half2_rn(eWc[j*64 + 2*L], eWc[j*64 + 2*L + 1]);
    float2 b1c = *(const float2*)&b1[128 + 2*L];
    float2 b2c = *(const float2*)&b2[128 + 2*L];
    float2 b3c = *(const float2*)&b3[128 + 2*L];

    float* st = sStg + w*256;
    uint2* mt = sMeta + w*32;
    for (int t = blockIdx.x*NWARP + w; t < NTASK; t += gridDim.x*NWARP) {
        int p0 = t*PT;
        int bb = p0 >> 13;
        const __half2* Fc = g_F1c + (size_t)bb*NN*32;
        #pragma unroll
        for (int q = 0; q < PT; q++) {
            int p = p0 + q;
            {
                int fi = nidx[(size_t)p*KK + L];
                const float* ep = ef + (size_t)p*96 + 3*L;
                __half2 e01 = __floats2half2_rn(ep[0], ep[1]);
                unsigned e2b = (unsigned)__half_as_ushort(__float2half_rn(ep[2]));
                mt[L] = make_uint2((unsigned)fi | (e2b << 16), *(const unsigned*)&e01);
            }
            __syncwarp();
            __half2 mc = __float2half2_rn(-6.0e4f);
            #pragma unroll 8
            for (int k = 0; k < KK; k++) {
                uint2 m = mt[k];
                int fi = (int)(m.x & 0xFFFFu);
                __half2 h2v = __half2half2(__ushort_as_half((unsigned short)(m.x >> 16)));
                __half2 e01 = *(const __half2*)&m.y;
                __half2 h0 = __low2half2(e01), h1 = __high2half2(e01);
                __half2 v = __ldg(&Fc[(size_t)fi*32 + L]);
                v = __hfma2(h0, wC[0], v);
                v = __hfma2(h1, wC[1], v);
                v = __hfma2(h2v, wC[2], v);
                mc = __hmax2(mc, v);
            }
            __syncwarp();
            float2 fc = __half22float2(mc);
            fc.x = lrelu(fc.x + b1c.x);  fc.y = lrelu(fc.y + b1c.y);
            *(float2*)&st[q*64 + 2*L] = fc;
        }
        __syncwarp();
        float yc[PT][2];
        #pragma unroll
        for (int q = 0; q < PT; q++) { yc[q][0] = b2c.x; yc[q][1] = b2c.y; }
        #pragma unroll 8
        for (int j = 0; j < 64; j++) {
            float2 wv = *(const float2*)&sW2[j*64 + 2*L];
            #pragma unroll
            for (int q = 0; q < PT; q++) {
                float pv = st[q*64 + j];
                yc[q][0] += pv*wv.x; yc[q][1] += pv*wv.y;
            }
        }
        __syncwarp();
        #pragma unroll
        for (int q = 0; q < PT; q++)
            *(float2*)&st[q*64 + 2*L] = make_float2(lrelu(yc[q][0]), lrelu(yc[q][1]));
        __syncwarp();
        float oc[PT][2];
        #pragma unroll
        for (int q = 0; q < PT; q++) { oc[q][0] = b3c.x; oc[q][1] = b3c.y; }
        #pragma unroll 8
        for (int j = 0; j < 64; j++) {
            float2 wv = *(const float2*)&sW3[j*64 + 2*L];
            #pragma unroll
            for (int q = 0; q < PT; q++) {
                float yv = st[q*64 + j];
                oc[q][0] += yv*wv.x; oc[q][1] += yv*wv.y;
            }
        }
        #pragma unroll
        for (int q = 0; q < PT; q++) {
            int p = p0 + q;
            float q0 = tanhf(oc[q][0]), q1 = tanhf(oc[q][1]);
            float2 zv = *(const float2*)&g_z[(size_t)p*64 + 2*L];
            float2 hv = *(const float2*)&h[(size_t)p*64 + 2*L];
            float o0 = hv.x + zv.x*(q0 - hv.x);
            float o1 = hv.y + zv.y*(q1 - hv.y);
            *(float2*)&out[(size_t)p*64 + 2*L] = make_float2(o0, o1);
        }
        __syncwarp();
    }
}

extern "C" void kernel_launch(void* const* d_in, const int* in_sizes, int n_in,
                              void* d_out, int out_size)
{
    const float* h   = (const float*)d_in[0];
    const float* x   = (const float*)d_in[1];
    // d_in[2] = c, unused (matches reference)
    const float* W1  = (const float*)d_in[3];
    const float* b1  = (const float*)d_in[4];
    const float* W2  = (const float*)d_in[5];
    const float* b2  = (const float*)d_in[6];
    const float* W3  = (const float*)d_in[7];
    const float* b3  = (const float*)d_in[8];
    const int*   nidx = (const int*)d_in[9];
    const float* ef  = (const float*)d_in[10];
    float* out = (float*)d_out;

    void *pF1ab, *pF1c, *pz, *prh;
    cudaGetSymbolAddress(&pF1ab, g_F1ab);
    cudaGetSymbolAddress(&pF1c,  g_F1c);
    cudaGetSymbolAddress(&pz,    g_z);
    cudaGetSymbolAddress(&prh,   g_rh);

    const int smem_l2h = (64*ASTR + 128*B2STR) * 2;           // 52224 B
    const int smem_l1h = (64*ASTR + 128*B1STR) * 2;           // 35840 B
    const int smem_g01 = (16384 + NWARP*512 + NWARP*64) * 4;  // 83968 B
    const int smem_g2  = (8192 + NWARP*256 + NWARP*64) * 4;   // 43008 B

    cudaFuncSetAttribute(linear2_hmma,  cudaFuncAttributeMaxDynamicSharedMemorySize, smem_l2h);
    cudaFuncSetAttribute(linear1_hmma,  cudaFuncAttributeMaxDynamicSharedMemorySize, smem_l1h);
    cudaFuncSetAttribute(gate01_kernel, cudaFuncAttributeMaxDynamicSharedMemorySize, smem_g01);
    cudaFuncSetAttribute(gate2_kernel,  cudaFuncAttributeMaxDynamicSharedMemorySize, smem_g2);

    dim3 blk(256);

    // F1ab = [h|x] @ {W1a[0], W1a[1]}  (HMMA, packed fp16 out)
    linear2_hmma<<<296, blk, smem_l2h>>>(h, x, W1, (unsigned*)pF1ab);
    // z, r*h  (512 blocks x 8 warps x 2 tasks = exactly 8192 tasks)
    gate01_kernel<<<512, blk, smem_g01>>>(h, W1, b1, W2, b2, W3, b3, nidx, ef,
                                          (float*)pz, (float*)prh);
    // F1c = [r*h|x] @ W1a[2]  (HMMA, fp16 out)
    linear1_hmma<<<296, blk, smem_l1h>>>((const float*)prh, x, W1, (unsigned*)pF1c);
    // q and final output
    gate2_kernel<<<512, blk, smem_g2>>>(h, W1, b1, W2, b2, W3, b3, nidx, ef, out);
}

// round 13
// speedup vs baseline: 2.3882x; 1.3320x over previous
#include <cuda_runtime.h>
#include <cuda_fp16.h>
#include <math.h>

#define BB 4
#define NN 8192
#define KK 32
#define BN (BB*NN)

// scratch (device globals; no allocation)
__device__ uint2   g_F1ab[BN*32];   // per point: {a-pair, b-pair} fp16 per group L
__device__ __half2 g_F1c[BN*32];
__device__ float   g_z[BN*64];
__device__ float   g_rh[BN*64];

__device__ __forceinline__ float lrelu(float v){ return v > 0.f ? v : 0.1f*v; }
__device__ __forceinline__ float sigm(float v){ return 1.f/(1.f+expf(-v)); }

// ---------------- tensor-core helpers (mma.sync HMMA) ----------------
__device__ __forceinline__ unsigned sm_u32(const void* p){
    return (unsigned)__cvta_generic_to_shared(p);
}
__device__ __forceinline__ void ldsm_x4(unsigned &r0, unsigned &r1, unsigned &r2, unsigned &r3,
                                        unsigned addr){
    asm volatile("ldmatrix.sync.aligned.m8n8.x4.shared.b16 {%0,%1,%2,%3}, [%4];"
        : "=r"(r0), "=r"(r1), "=r"(r2), "=r"(r3) : "r"(addr));
}
__device__ __forceinline__ void ldsm_x4_t(unsigned &r0, unsigned &r1, unsigned &r2, unsigned &r3,
                                          unsigned addr){
    asm volatile("ldmatrix.sync.aligned.m8n8.x4.trans.shared.b16 {%0,%1,%2,%3}, [%4];"
        : "=r"(r0), "=r"(r1), "=r"(r2), "=r"(r3) : "r"(addr));
}
__device__ __forceinline__ void mma16816(float* c,
        unsigned a0, unsigned a1, unsigned a2, unsigned a3,
        unsigned b0, unsigned b1){
    asm volatile("mma.sync.aligned.m16n8k16.row.col.f32.f16.f16.f32 "
        "{%0,%1,%2,%3}, {%4,%5,%6,%7}, {%8,%9}, {%0,%1,%2,%3};"
        : "+f"(c[0]), "+f"(c[1]), "+f"(c[2]), "+f"(c[3])
        : "r"(a0), "r"(a1), "r"(a2), "r"(a3), "r"(b0), "r"(b1));
}

#define ASTR 136
#define B2STR 136
#define B1STR 72
#define PSTR 72          // padded row stride (halfs) for 64-wide fp16 tiles

// ---------------- linear2 (HMMA): F1ab = [h|x] @ {W1a[0],W1a[1]} ----------------
__global__ void __launch_bounds__(256)
linear2_hmma(const float* __restrict__ s0, const float* __restrict__ s1,
             const float* __restrict__ W1, unsigned* __restrict__ out32)
{
    extern __shared__ __half smh[];
    __half* A = smh;                 // 64 x ASTR
    __half* B = smh + 64*ASTR;       // 128 x B2STR
    int tid = threadIdx.x, w = tid>>5, L = tid&31;
    int wm = w >> 1, wn = w & 1;     // 4 m-warps x 2 n-warps

    const float* Wa = W1;
    const float* Wb = W1 + 131*64;
    for (int i = tid; i < 128*64; i += 256) {
        int k = i >> 6, n = i & 63;
        B[k*B2STR + n]      = __float2half_rn(Wa[k*64 + n]);
        B[k*B2STR + 64 + n] = __float2half_rn(Wb[k*64 + n]);
    }
    __syncthreads();

    int r = L >> 2, cq = (L & 3) * 2;
    for (int tile = blockIdx.x; tile < BN/64; tile += gridDim.x) {
        int pt0 = tile * 64;
        for (int i = tid; i < 64*64; i += 256) {
            int p = i >> 6, c2 = i & 63;
            float2 v = (c2 < 32) ? *(const float2*)&s0[(size_t)(pt0+p)*64 + 2*c2]
                                 : *(const float2*)&s1[(size_t)(pt0+p)*64 + 2*(c2-32)];
            *(__half2*)&A[p*ASTR + 2*c2] = __floats2half2_rn(v.x, v.y);
        }
        __syncthreads();

        float C[8][4];
        #pragma unroll
        for (int i = 0; i < 8; i++)
            #pragma unroll
            for (int j = 0; j < 4; j++) C[i][j] = 0.f;

        #pragma unroll
        for (int ks = 0; ks < 8; ks++) {
            int k0 = ks * 16;
            unsigned a0,a1,a2,a3;
            ldsm_x4(a0,a1,a2,a3, sm_u32(&A[(wm*16 + (L&15))*ASTR + k0 + (L>>4)*8]));
            #pragma unroll
            for (int nt = 0; nt < 4; nt++) {
                unsigned b0,b1,b2,b3;
                ldsm_x4_t(b0,b1,b2,b3,
                    sm_u32(&B[(k0 + (L&15))*B2STR + wn*64 + nt*16 + (L>>4)*8]));
                mma16816(C[2*nt],   a0,a1,a2,a3, b0,b1);
                mma16816(C[2*nt+1], a0,a1,a2,a3, b2,b3);
            }
        }
        #pragma unroll
        for (int nt8 = 0; nt8 < 8; nt8++) {
            int col = wn*64 + nt8*8 + cq;
            int oidx = (col < 64) ? col : (col - 63);
            int p = pt0 + wm*16 + r;
            __half2 lo = __floats2half2_rn(C[nt8][0], C[nt8][1]);
            __half2 hi = __floats2half2_rn(C[nt8][2], C[nt8][3]);
            out32[(size_t)p*64 + oidx]     = *(const unsigned*)&lo;
            out32[(size_t)(p+8)*64 + oidx] = *(const unsigned*)&hi;
        }
        __syncthreads();
    }
}

// ---------------- linear1 (HMMA): F1c = [rh|x] @ W1a[2] ----------------
__global__ void __launch_bounds__(256)
linear1_hmma(const float* __restrict__ s0, const float* __restrict__ s1,
             const float* __restrict__ W1, unsigned* __restrict__ out32)
{
    extern __shared__ __half smh[];
    __half* A = smh;
    __half* B = smh + 64*ASTR;
    int tid = threadIdx.x, w = tid>>5, L = tid&31;
    int wm = w >> 1, wn = w & 1;

    const float* Wc = W1 + 2*131*64;
    for (int i = tid; i < 128*64; i += 256) {
        int k = i >> 6, n = i & 63;
        B[k*B1STR + n] = __float2half_rn(Wc[k*64 + n]);
    }
    __syncthreads();

    int r = L >> 2, cq = (L & 3) * 2;
    for (int tile = blockIdx.x; tile < BN/64; tile += gridDim.x) {
        int pt0 = tile * 64;
        for (int i = tid; i < 64*64; i += 256) {
            int p = i >> 6, c2 = i & 63;
            float2 v = (c2 < 32) ? *(const float2*)&s0[(size_t)(pt0+p)*64 + 2*c2]
                                 : *(const float2*)&s1[(size_t)(pt0+p)*64 + 2*(c2-32)];
            *(__half2*)&A[p*ASTR + 2*c2] = __floats2half2_rn(v.x, v.y);
        }
        __syncthreads();

        float C[4][4];
        #pragma unroll
        for (int i = 0; i < 4; i++)
            #pragma unroll
            for (int j = 0; j < 4; j++) C[i][j] = 0.f;

        #pragma unroll
        for (int ks = 0; ks < 8; ks++) {
            int k0 = ks * 16;
            unsigned a0,a1,a2,a3;
            ldsm_x4(a0,a1,a2,a3, sm_u32(&A[(wm*16 + (L&15))*ASTR + k0 + (L>>4)*8]));
            #pragma unroll
            for (int nt = 0; nt < 2; nt++) {
                unsigned b0,b1,b2,b3;
                ldsm_x4_t(b0,b1,b2,b3,
                    sm_u32(&B[(k0 + (L&15))*B1STR + wn*32 + nt*16 + (L>>4)*8]));
                mma16816(C[2*nt],   a0,a1,a2,a3, b0,b1);
                mma16816(C[2*nt+1], a0,a1,a2,a3, b2,b3);
            }
        }
        #pragma unroll
        for (int nt8 = 0; nt8 < 4; nt8++) {
            int col = wn*32 + nt8*8 + cq;
            int p = pt0 + wm*16 + r;
            __half2 lo = __floats2half2_rn(C[nt8][0], C[nt8][1]);
            __half2 hi = __floats2half2_rn(C[nt8][2], C[nt8][3]);
            out32[(size_t)p*32 + (col>>1)]     = *(const unsigned*)&lo;
            out32[(size_t)(p+8)*32 + (col>>1)] = *(const unsigned*)&hi;
        }
        __syncthreads();
    }
}

// ---------------- gate01 (HMMA MLP): branches 0+1 -> z, r*h ----------------
// tile = 64 points, 8 warps: gather 8 pts/warp, then 2-layer MLP on tensor pipe.
__global__ void __launch_bounds__(256)
gate01_hmma(const float* __restrict__ h,
    const float* __restrict__ W1, const float* __restrict__ b1,
    const float* __restrict__ W2, const float* __restrict__ b2,
    const float* __restrict__ W3, const float* __restrict__ b3,
    const int* __restrict__ nidx, const float* __restrict__ ef,
    float* __restrict__ z_out, float* __restrict__ rh_out)
{
    extern __shared__ __half smh[];
    __half* sW2 = smh;                 // 2 x [64 x PSTR]
    __half* sW3 = smh + 2*64*PSTR;     // 2 x [64 x PSTR]
    __half* P   = smh + 4*64*PSTR;     // 2 x [64 x PSTR]  (PA, PB)
    uint2* mt_all = (uint2*)(smh + 6*64*PSTR);
    int tid = threadIdx.x, w = tid>>5, L = tid&31;

    for (int i = tid; i < 2*64*64; i += 256) {
        int br = i >> 12, rem = i & 4095, j = rem >> 6, d = rem & 63;
        sW2[br*64*PSTR + j*PSTR + d] = __float2half_rn(W2[br*4096 + j*64 + d]);
        sW3[br*64*PSTR + j*PSTR + d] = __float2half_rn(W3[br*4096 + j*64 + d]);
    }
    __syncthreads();

    const float* eWa = W1 + 128*64;
    const float* eWb = W1 + 131*64 + 128*64;
    __half2 wA[3], wB[3];
    #pragma unroll
    for (int j = 0; j < 3; j++) {
        wA[j] = __floats2half2_rn(eWa[j*64 + 2*L], eWa[j*64 + 2*L + 1]);
        wB[j] = __floats2half2_rn(eWb[j*64 + 2*L], eWb[j*64 + 2*L + 1]);
    }
    float2 b1a = *(const float2*)&b1[2*L], b1b = *(const float2*)&b1[64 + 2*L];

    int pt0 = blockIdx.x * 64;
    int bb = pt0 >> 13;
    const uint2* Fab = g_F1ab + (size_t)bb*NN*32;
    __half* PA = P;
    __half* PB = P + 64*PSTR;
    uint2* mt = mt_all + w*32;

    // ---- phase 1: gather + pool ----
    for (int qq = 0; qq < 8; qq++) {
        int pl = w*8 + qq;
        int p  = pt0 + pl;
        {
            int fi = nidx[(size_t)p*KK + L];
            const float* ep = ef + (size_t)p*96 + 3*L;
            __half2 e01 = __floats2half2_rn(ep[0], ep[1]);
            unsigned e2b = (unsigned)__half_as_ushort(__float2half_rn(ep[2]));
            mt[L] = make_uint2((unsigned)fi | (e2b << 16), *(const unsigned*)&e01);
        }
        __syncwarp();
        __half2 ma = __float2half2_rn(-6.0e4f), mb = ma;
        #pragma unroll 8
        for (int k = 0; k < KK; k++) {
            uint2 m = mt[k];
            int fi = (int)(m.x & 0xFFFFu);
            __half2 h2v = __half2half2(__ushort_as_half((unsigned short)(m.x >> 16)));
            __half2 e01 = *(const __half2*)&m.y;
            __half2 h0 = __low2half2(e01), h1 = __high2half2(e01);
            uint2 v = __ldg(&Fab[(size_t)fi*32 + L]);
            __half2 ta = *(const __half2*)&v.x;
            ta = __hfma2(h0, wA[0], ta);
            ta = __hfma2(h1, wA[1], ta);
            ta = __hfma2(h2v, wA[2], ta);
            ma = __hmax2(ma, ta);
            __half2 tb = *(const __half2*)&v.y;
            tb = __hfma2(h0, wB[0], tb);
            tb = __hfma2(h1, wB[1], tb);
            tb = __hfma2(h2v, wB[2], tb);
            mb = __hmax2(mb, tb);
        }
        __syncwarp();
        float2 fa = __half22float2(ma), fb = __half22float2(mb);
        fa.x = lrelu(fa.x + b1a.x);  fa.y = lrelu(fa.y + b1a.y);
        fb.x = lrelu(fb.x + b1b.x);  fb.y = lrelu(fb.y + b1b.y);
        *(__half2*)&PA[pl*PSTR + 2*L] = __floats2half2_rn(fa.x, fa.y);
        *(__half2*)&PB[pl*PSTR + 2*L] = __floats2half2_rn(fb.x, fb.y);
    }
    __syncthreads();

    // ---- phase 2: MLP on tensor pipe ----
    int wbr = w >> 2, wm = w & 3;        // 4 m-warps per branch
    __half* Pb  = P   + wbr*64*PSTR;
    __half* W2b = sW2 + wbr*64*PSTR;
    __half* W3b = sW3 + wbr*64*PSTR;
    int r = L >> 2, cq = (L & 3) * 2;
    const float* b2v = b2 + wbr*64;
    const float* b3v = b3 + wbr*64;

    // layer 1
    float C[8][4];
    #pragma unroll
    for (int i = 0; i < 8; i++)
        #pragma unroll
        for (int j = 0; j < 4; j++) C[i][j] = 0.f;
    #pragma unroll
    for (int ks = 0; ks < 4; ks++) {
        int k0 = ks * 16;
        unsigned a0,a1,a2,a3;
        ldsm_x4(a0,a1,a2,a3, sm_u32(&Pb[(wm*16 + (L&15))*PSTR + k0 + (L>>4)*8]));
        #pragma unroll
        for (int nt = 0; nt < 4; nt++) {
            unsigned b0v,b1v,b2q,b3q;
            ldsm_x4_t(b0v,b1v,b2q,b3q,
                sm_u32(&W2b[(k0 + (L&15))*PSTR + nt*16 + (L>>4)*8]));
            mma16816(C[2*nt],   a0,a1,a2,a3, b0v,b1v);
            mma16816(C[2*nt+1], a0,a1,a2,a3, b2q,b3q);
        }
    }
    __syncthreads();   // all ldsm of P complete -> safe to overwrite
    #pragma unroll
    for (int nt8 = 0; nt8 < 8; nt8++) {
        int col = nt8*8 + cq;
        float c0 = lrelu(C[nt8][0] + __ldg(&b2v[col]));
        float c1 = lrelu(C[nt8][1] + __ldg(&b2v[col+1]));
        float c2 = lrelu(C[nt8][2] + __ldg(&b2v[col]));
        float c3 = lrelu(C[nt8][3] + __ldg(&b2v[col+1]));
        *(__half2*)&Pb[(wm*16 + r)*PSTR + col]     = __floats2half2_rn(c0, c1);
        *(__half2*)&Pb[(wm*16 + r + 8)*PSTR + col] = __floats2half2_rn(c2, c3);
    }
    __syncthreads();

    // layer 2
    #pragma unroll
    for (int i = 0; i < 8; i++)
        #pragma unroll
        for (int j = 0; j < 4; j++) C[i][j] = 0.f;
    #pragma unroll
    for (int ks = 0; ks < 4; ks++) {
        int k0 = ks * 16;
        unsigned a0,a1,a2,a3;
        ldsm_x4(a0,a1,a2,a3, sm_u32(&Pb[(wm*16 + (L&15))*PSTR + k0 + (L>>4)*8]));
        #pragma unroll
        for (int nt = 0; nt < 4; nt++) {
            unsigned b0v,b1v,b2q,b3q;
            ldsm_x4_t(b0v,b1v,b2q,b3q,
                sm_u32(&W3b[(k0 + (L&15))*PSTR + nt*16 + (L>>4)*8]));
            mma16816(C[2*nt],   a0,a1,a2,a3, b0v,b1v);
            mma16816(C[2*nt+1], a0,a1,a2,a3, b2q,b3q);
        }
    }
    // final epilogue
    #pragma unroll
    for (int nt8 = 0; nt8 < 8; nt8++) {
        int col = nt8*8 + cq;
        int pLo = pt0 + wm*16 + r;
        int pHi = pLo + 8;
        float c0 = sigm(C[nt8][0] + __ldg(&b3v[col]));
        float c1 = sigm(C[nt8][1] + __ldg(&b3v[col+1]));
        float c2 = sigm(C[nt8][2] + __ldg(&b3v[col]));
        float c3 = sigm(C[nt8][3] + __ldg(&b3v[col+1]));
        if (wbr == 0) {
            *(float2*)&z_out[(size_t)pLo*64 + col] = make_float2(c0, c1);
            *(float2*)&z_out[(size_t)pHi*64 + col] = make_float2(c2, c3);
        } else {
            float2 hLo = *(const float2*)&h[(size_t)pLo*64 + col];
            float2 hHi = *(const float2*)&h[(size_t)pHi*64 + col];
            *(float2*)&rh_out[(size_t)pLo*64 + col] = make_float2(c0*hLo.x, c1*hLo.y);
            *(float2*)&rh_out[(size_t)pHi*64 + col] = make_float2(c2*hHi.x, c3*hHi.y);
        }
    }
}

// ---------------- gate2 (HMMA MLP): branch 2 -> q; out = h + z*(q-h) ----------------
// tile = 128 points, 8 warps: gather 16 pts/warp, then 2-layer MLP (M=128).
__global__ void __launch_bounds__(256)
gate2_hmma(const float* __restrict__ h,
    const float* __restrict__ W1, const float* __restrict__ b1,
    const float* __restrict__ W2, const float* __restrict__ b2,
    const float* __restrict__ W3, const float* __restrict__ b3,
    const int* __restrict__ nidx, const float* __restrict__ ef,
    float* __restrict__ out)
{
    extern __shared__ __half smh[];
    __half* sW2 = smh;                 // [64 x PSTR]
    __half* sW3 = smh + 64*PSTR;       // [64 x PSTR]
    __half* P   = smh + 2*64*PSTR;     // [128 x PSTR]
    uint2* mt_all = (uint2*)(smh + 4*64*PSTR);
    int tid = threadIdx.x, w = tid>>5, L = tid&31;

    for (int i = tid; i < 64*64; i += 256) {
        int j = i >> 6, d = i & 63;
        sW2[j*PSTR + d] = __float2half_rn(W2[2*4096 + j*64 + d]);
        sW3[j*PSTR + d] = __float2half_rn(W3[2*4096 + j*64 + d]);
    }
    __syncthreads();

    const float* eWc = W1 + 2*131*64 + 128*64;
    __half2 wC[3];
    #pragma unroll
    for (int j = 0; j < 3; j++)
        wC[j] = __floats2half2_rn(eWc[j*64 + 2*L], eWc[j*64 + 2*L + 1]);
    float2 b1c = *(const float2*)&b1[128 + 2*L];

    int pt0 = blockIdx.x * 128;
    int bb = pt0 >> 13;
    const __half2* Fc = g_F1c + (size_t)bb*NN*32;
    uint2* mt = mt_all + w*32;

    // ---- phase 1: gather + pool ----
    for (int qq = 0; qq < 16; qq++) {
        int pl = w*16 + qq;
        int p  = pt0 + pl;
        {
            int fi = nidx[(size_t)p*KK + L];
            const float* ep = ef + (size_t)p*96 + 3*L;
            __half2 e01 = __floats2half2_rn(ep[0], ep[1]);
            unsigned e2b = (unsigned)__half_as_ushort(__float2half_rn(ep[2]));
            mt[L] = make_uint2((unsigned)fi | (e2b << 16), *(const unsigned*)&e01);
        }
        __syncwarp();
        __half2 mc = __float2half2_rn(-6.0e4f);
        #pragma unroll 8
        for (int k = 0; k < KK; k++) {
            uint2 m = mt[k];
            int fi = (int)(m.x & 0xFFFFu);
            __half2 h2v = __half2half2(__ushort_as_half((unsigned short)(m.x >> 16)));
            __half2 e01 = *(const __half2*)&m.y;
            __half2 h0 = __low2half2(e01), h1 = __high2half2(e01);
            __half2 v = __ldg(&Fc[(size_t)fi*32 + L]);
            v = __hfma2(h0, wC[0], v);
            v = __hfma2(h1, wC[1], v);
            v = __hfma2(h2v, wC[2], v);
            mc = __hmax2(mc, v);
        }
        __syncwarp();
        float2 fc = __half22float2(mc);
        fc.x = lrelu(fc.x + b1c.x);  fc.y = lrelu(fc.y + b1c.y);
        *(__half2*)&P[pl*PSTR + 2*L] = __floats2half2_rn(fc.x, fc.y);
    }
    __syncthreads();

    // ---- phase 2: MLP (M=128, one 16-row band per warp) ----
    int r = L >> 2, cq = (L & 3) * 2;
    const float* b2v = b2 + 128;
    const float* b3v = b3 + 128;

    float C[8][4];
    #pragma unroll
    for (int i = 0; i < 8; i++)
        #pragma unroll
        for (int j = 0; j < 4; j++) C[i][j] = 0.f;
    #pragma unroll
    for (int ks = 0; ks < 4; ks++) {
        int k0 = ks * 16;
        unsigned a0,a1,a2,a3;
        ldsm_x4(a0,a1,a2,a3, sm_u32(&P[(w*16 + (L&15))*PSTR + k0 + (L>>4)*8]));
        #pragma unroll
        for (int nt = 0; nt < 4; nt++) {
            unsigned b0v,b1v,b2q,b3q;
            ldsm_x4_t(b0v,b1v,b2q,b3q,
                sm_u32(&sW2[(k0 + (L&15))*PSTR + nt*16 + (L>>4)*8]));
            mma16816(C[2*nt],   a0,a1,a2,a3, b0v,b1v);
            mma16816(C[2*nt+1], a0,a1,a2,a3, b2q,b3q);
        }
    }
    __syncthreads();
    #pragma unroll
    for (int nt8 = 0; nt8 < 8; nt8++) {
        int col = nt8*8 + cq;
        float c0 = lrelu(C[nt8][0] + __ldg(&b2v[col]));
        float c1 = lrelu(C[nt8][1] + __ldg(&b2v[col+1]));
        float c2 = lrelu(C[nt8][2] + __ldg(&b2v[col]));
        float c3 = lrelu(C[nt8][3] + __ldg(&b2v[col+1]));
        *(__half2*)&P[(w*16 + r)*PSTR + col]     = __floats2half2_rn(c0, c1);
        *(__half2*)&P[(w*16 + r + 8)*PSTR + col] = __floats2half2_rn(c2, c3);
    }
    __syncthreads();

    #pragma unroll
    for (int i = 0; i < 8; i++)
        #pragma unroll
        for (int j = 0; j < 4; j++) C[i][j] = 0.f;
    #pragma unroll
    for (int ks = 0; ks < 4; ks++) {
        int k0 = ks * 16;
        unsigned a0,a1,a2,a3;
        ldsm_x4(a0,a1,a2,a3, sm_u32(&P[(w*16 + (L&15))*PSTR + k0 + (L>>4)*8]));
        #pragma unroll
        for (int nt = 0; nt < 4; nt++) {
            unsigned b0v,b1v,b2q,b3q;
            ldsm_x4_t(b0v,b1v,b2q,b3q,
                sm_u32(&sW3[(k0 + (L&15))*PSTR + nt*16 + (L>>4)*8]));
            mma16816(C[2*nt],   a0,a1,a2,a3, b0v,b1v);
            mma16816(C[2*nt+1], a0,a1,a2,a3, b2q,b3q);
        }
    }
    #pragma unroll
    for (int nt8 = 0; nt8 < 8; nt8++) {
        int col = nt8*8 + cq;
        int pLo = pt0 + w*16 + r;
        int pHi = pLo + 8;
        float q0 = tanhf(C[nt8][0] + __ldg(&b3v[col]));
        float q1 = tanhf(C[nt8][1] + __ldg(&b3v[col+1]));
        float q2 = tanhf(C[nt8][2] + __ldg(&b3v[col]));
        float q3 = tanhf(C[nt8][3] + __ldg(&b3v[col+1]));
        float2 zLo = *(const float2*)&g_z[(size_t)pLo*64 + col];
        float2 zHi = *(const float2*)&g_z[(size_t)pHi*64 + col];
        float2 hLo = *(const float2*)&h[(size_t)pLo*64 + col];
        float2 hHi = *(const float2*)&h[(size_t)pHi*64 + col];
        *(float2*)&out[(size_t)pLo*64 + col] =
            make_float2(hLo.x + zLo.x*(q0 - hLo.x), hLo.y + zLo.y*(q1 - hLo.y));
        *(float2*)&out[(size_t)pHi*64 + col] =
            make_float2(hHi.x + zHi.x*(q2 - hHi.x), hHi.y + zHi.y*(q3 - hHi.y));
    }
}

extern "C" void kernel_launch(void* const* d_in, const int* in_sizes, int n_in,
                              void* d_out, int out_size)
{
    const float* h   = (const float*)d_in[0];
    const float* x   = (const float*)d_in[1];
    // d_in[2] = c, unused (matches reference)
    const float* W1  = (const float*)d_in[3];
    const float* b1  = (const float*)d_in[4];
    const float* W2  = (const float*)d_in[5];
    const float* b2  = (const float*)d_in[6];
    const float* W3  = (const float*)d_in[7];
    const float* b3  = (const float*)d_in[8];
    const int*   nidx = (const int*)d_in[9];
    const float* ef  = (const float*)d_in[10];
    float* out = (float*)d_out;

    void *pF1ab, *pF1c, *pz, *prh;
    cudaGetSymbolAddress(&pF1ab, g_F1ab);
    cudaGetSymbolAddress(&pF1c,  g_F1c);
    cudaGetSymbolAddress(&pz,    g_z);
    cudaGetSymbolAddress(&prh,   g_rh);

    const int smem_l2h = (64*ASTR + 128*B2STR) * 2;        // 52224 B
    const int smem_l1h = (64*ASTR + 128*B1STR) * 2;        // 35840 B
    const int smem_g01 = 6*64*PSTR*2 + 8*32*8;             // 57344 B
    const int smem_g2  = 4*64*PSTR*2 + 8*32*8;             // 38912 B

    cudaFuncSetAttribute(linear2_hmma, cudaFuncAttributeMaxDynamicSharedMemorySize, smem_l2h);
    cudaFuncSetAttribute(linear1_hmma, cudaFuncAttributeMaxDynamicSharedMemorySize, smem_l1h);
    cudaFuncSetAttribute(gate01_hmma,  cudaFuncAttributeMaxDynamicSharedMemorySize, smem_g01);
    cudaFuncSetAttribute(gate2_hmma,   cudaFuncAttributeMaxDynamicSharedMemorySize, smem_g2);

    dim3 blk(256);

    // F1ab = [h|x] @ {W1a[0], W1a[1]}  (HMMA, packed fp16 out)
    linear2_hmma<<<296, blk, smem_l2h>>>(h, x, W1, (unsigned*)pF1ab);
    // z, r*h  (512 tiles of 64 points)
    gate01_hmma<<<512, blk, smem_g01>>>(h, W1, b1, W2, b2, W3, b3, nidx, ef,
                                        (float*)pz, (float*)prh);
    // F1c = [r*h|x] @ W1a[2]  (HMMA, fp16 out)
    linear1_hmma<<<296, blk, smem_l1h>>>((const float*)prh, x, W1, (unsigned*)pF1c);
    // q and final output  (256 tiles of 128 points)
    gate2_hmma<<<256, blk, smem_g2>>>(h, W1, b1, W2, b2, W3, b3, nidx, ef, out);
}

// round 14
// speedup vs baseline: 2.5399x; 1.0635x over previous
#include <cuda_runtime.h>
#include <cuda_fp16.h>
#include <math.h>

#define BB 4
#define NN 8192
#define KK 32
#define BN (BB*NN)

// scratch (device globals; no allocation)
__device__ uint2   g_F1ab[BN*32];   // per point: {a-pair, b-pair} fp16 per group L
__device__ __half2 g_F1c[BN*32];
__device__ float   g_z[BN*64];
__device__ float   g_rh[BN*64];

__device__ __forceinline__ float lrelu(float v){ return v > 0.f ? v : 0.1f*v; }
__device__ __forceinline__ float sigm(float v){ return 1.f/(1.f+expf(-v)); }

// ---------------- tensor-core helpers (mma.sync HMMA) ----------------
__device__ __forceinline__ unsigned sm_u32(const void* p){
    return (unsigned)__cvta_generic_to_shared(p);
}
__device__ __forceinline__ void ldsm_x4(unsigned &r0, unsigned &r1, unsigned &r2, unsigned &r3,
                                        unsigned addr){
    asm volatile("ldmatrix.sync.aligned.m8n8.x4.shared.b16 {%0,%1,%2,%3}, [%4];"
        : "=r"(r0), "=r"(r1), "=r"(r2), "=r"(r3) : "r"(addr));
}
__device__ __forceinline__ void ldsm_x4_t(unsigned &r0, unsigned &r1, unsigned &r2, unsigned &r3,
                                          unsigned addr){
    asm volatile("ldmatrix.sync.aligned.m8n8.x4.trans.shared.b16 {%0,%1,%2,%3}, [%4];"
        : "=r"(r0), "=r"(r1), "=r"(r2), "=r"(r3) : "r"(addr));
}
__device__ __forceinline__ void mma16816(float* c,
        unsigned a0, unsigned a1, unsigned a2, unsigned a3,
        unsigned b0, unsigned b1){
    asm volatile("mma.sync.aligned.m16n8k16.row.col.f32.f16.f16.f32 "
        "{%0,%1,%2,%3}, {%4,%5,%6,%7}, {%8,%9}, {%0,%1,%2,%3};"
        : "+f"(c[0]), "+f"(c[1]), "+f"(c[2]), "+f"(c[3])
        : "r"(a0), "r"(a1), "r"(a2), "r"(a3), "r"(b0), "r"(b1));
}

#define ASTR 136
#define B2STR 136
#define B1STR 72
#define PSTR 72          // padded row stride (halfs) for 64-wide fp16 tiles

// ---------------- linear2 (HMMA): F1ab = [h|x] @ {W1a[0],W1a[1]} ----------------
__global__ void __launch_bounds__(256)
linear2_hmma(const float* __restrict__ s0, const float* __restrict__ s1,
             const float* __restrict__ W1, unsigned* __restrict__ out32)
{
    extern __shared__ __half smh[];
    __half* A = smh;                 // 64 x ASTR
    __half* B = smh + 64*ASTR;       // 128 x B2STR
    int tid = threadIdx.x, w = tid>>5, L = tid&31;
    int wm = w >> 1, wn = w & 1;     // 4 m-warps x 2 n-warps

    const float* Wa = W1;
    const float* Wb = W1 + 131*64;
    for (int i = tid; i < 128*64; i += 256) {
        int k = i >> 6, n = i & 63;
        B[k*B2STR + n]      = __float2half_rn(Wa[k*64 + n]);
        B[k*B2STR + 64 + n] = __float2half_rn(Wb[k*64 + n]);
    }
    __syncthreads();

    int r = L >> 2, cq = (L & 3) * 2;
    for (int tile = blockIdx.x; tile < BN/64; tile += gridDim.x) {
        int pt0 = tile * 64;
        for (int i = tid; i < 64*64; i += 256) {
            int p = i >> 6, c2 = i & 63;
            float2 v = (c2 < 32) ? *(const float2*)&s0[(size_t)(pt0+p)*64 + 2*c2]
                                 : *(const float2*)&s1[(size_t)(pt0+p)*64 + 2*(c2-32)];
            *(__half2*)&A[p*ASTR + 2*c2] = __floats2half2_rn(v.x, v.y);
        }
        __syncthreads();

        float C[8][4];
        #pragma unroll
        for (int i = 0; i < 8; i++)
            #pragma unroll
            for (int j = 0; j < 4; j++) C[i][j] = 0.f;

        #pragma unroll
        for (int ks = 0; ks < 8; ks++) {
            int k0 = ks * 16;
            unsigned a0,a1,a2,a3;
            ldsm_x4(a0,a1,a2,a3, sm_u32(&A[(wm*16 + (L&15))*ASTR + k0 + (L>>4)*8]));
            #pragma unroll
            for (int nt = 0; nt < 4; nt++) {
                unsigned b0,b1,b2,b3;
                ldsm_x4_t(b0,b1,b2,b3,
                    sm_u32(&B[(k0 + (L&15))*B2STR + wn*64 + nt*16 + (L>>4)*8]));
                mma16816(C[2*nt],   a0,a1,a2,a3, b0,b1);
                mma16816(C[2*nt+1], a0,a1,a2,a3, b2,b3);
            }
        }
        #pragma unroll
        for (int nt8 = 0; nt8 < 8; nt8++) {
            int col = wn*64 + nt8*8 + cq;
            int oidx = (col < 64) ? col : (col - 63);
            int p = pt0 + wm*16 + r;
            __half2 lo = __floats2half2_rn(C[nt8][0], C[nt8][1]);
            __half2 hi = __floats2half2_rn(C[nt8][2], C[nt8][3]);
            out32[(size_t)p*64 + oidx]     = *(const unsigned*)&lo;
            out32[(size_t)(p+8)*64 + oidx] = *(const unsigned*)&hi;
        }
        __syncthreads();
    }
}

// ---------------- linear1 (HMMA): F1c = [rh|x] @ W1a[2] ----------------
__global__ void __launch_bounds__(256)
linear1_hmma(const float* __restrict__ s0, const float* __restrict__ s1,
             const float* __restrict__ W1, unsigned* __restrict__ out32)
{
    extern __shared__ __half smh[];
    __half* A = smh;
    __half* B = smh + 64*ASTR;
    int tid = threadIdx.x, w = tid>>5, L = tid&31;
    int wm = w >> 1, wn = w & 1;

    const float* Wc = W1 + 2*131*64;
    for (int i = tid; i < 128*64; i += 256) {
        int k = i >> 6, n = i & 63;
        B[k*B1STR + n] = __float2half_rn(Wc[k*64 + n]);
    }
    __syncthreads();

    int r = L >> 2, cq = (L & 3) * 2;
    for (int tile = blockIdx.x; tile < BN/64; tile += gridDim.x) {
        int pt0 = tile * 64;
        for (int i = tid; i < 64*64; i += 256) {
            int p = i >> 6, c2 = i & 63;
            float2 v = (c2 < 32) ? *(const float2*)&s0[(size_t)(pt0+p)*64 + 2*c2]
                                 : *(const float2*)&s1[(size_t)(pt0+p)*64 + 2*(c2-32)];
            *(__half2*)&A[p*ASTR + 2*c2] = __floats2half2_rn(v.x, v.y);
        }
        __syncthreads();

        float C[4][4];
        #pragma unroll
        for (int i = 0; i < 4; i++)
            #pragma unroll
            for (int j = 0; j < 4; j++) C[i][j] = 0.f;

        #pragma unroll
        for (int ks = 0; ks < 8; ks++) {
            int k0 = ks * 16;
            unsigned a0,a1,a2,a3;
            ldsm_x4(a0,a1,a2,a3, sm_u32(&A[(wm*16 + (L&15))*ASTR + k0 + (L>>4)*8]));
            #pragma unroll
            for (int nt = 0; nt < 2; nt++) {
                unsigned b0,b1,b2,b3;
                ldsm_x4_t(b0,b1,b2,b3,
                    sm_u32(&B[(k0 + (L&15))*B1STR + wn*32 + nt*16 + (L>>4)*8]));
                mma16816(C[2*nt],   a0,a1,a2,a3, b0,b1);
                mma16816(C[2*nt+1], a0,a1,a2,a3, b2,b3);
            }
        }
        #pragma unroll
        for (int nt8 = 0; nt8 < 4; nt8++) {
            int col = wn*32 + nt8*8 + cq;
            int p = pt0 + wm*16 + r;
            __half2 lo = __floats2half2_rn(C[nt8][0], C[nt8][1]);
            __half2 hi = __floats2half2_rn(C[nt8][2], C[nt8][3]);
            out32[(size_t)p*32 + (col>>1)]     = *(const unsigned*)&lo;
            out32[(size_t)(p+8)*32 + (col>>1)] = *(const unsigned*)&hi;
        }
        __syncthreads();
    }
}

// ---------------- gate01 (HMMA MLP): branches 0+1 -> z, r*h ----------------
// tile = 64 points, 8 warps: gather 8 pts/warp, then 2-layer MLP on tensor pipe.
__global__ void __launch_bounds__(256)
gate01_hmma(const float* __restrict__ h,
    const float* __restrict__ W1, const float* __restrict__ b1,
    const float* __restrict__ W2, const float* __restrict__ b2,
    const float* __restrict__ W3, const float* __restrict__ b3,
    const int* __restrict__ nidx, const float* __restrict__ ef,
    float* __restrict__ z_out, float* __restrict__ rh_out)
{
    extern __shared__ __half smh[];
    __half* sW2 = smh;                 // 2 x [64 x PSTR]
    __half* sW3 = smh + 2*64*PSTR;     // 2 x [64 x PSTR]
    __half* P   = smh + 4*64*PSTR;     // 2 x [64 x PSTR]  (PA, PB)
    uint2* mt_all = (uint2*)(smh + 6*64*PSTR);
    int tid = threadIdx.x, w = tid>>5, L = tid&31;

    for (int i = tid; i < 2*64*64; i += 256) {
        int br = i >> 12, rem = i & 4095, j = rem >> 6, d = rem & 63;
        sW2[br*64*PSTR + j*PSTR + d] = __float2half_rn(W2[br*4096 + j*64 + d]);
        sW3[br*64*PSTR + j*PSTR + d] = __float2half_rn(W3[br*4096 + j*64 + d]);
    }
    __syncthreads();

    const float* eWa = W1 + 128*64;
    const float* eWb = W1 + 131*64 + 128*64;
    __half2 wA[3], wB[3];
    #pragma unroll
    for (int j = 0; j < 3; j++) {
        wA[j] = __floats2half2_rn(eWa[j*64 + 2*L], eWa[j*64 + 2*L + 1]);
        wB[j] = __floats2half2_rn(eWb[j*64 + 2*L], eWb[j*64 + 2*L + 1]);
    }
    float2 b1a = *(const float2*)&b1[2*L], b1b = *(const float2*)&b1[64 + 2*L];

    int pt0 = blockIdx.x * 64;
    int bb = pt0 >> 13;
    const uint2* Fab = g_F1ab + (size_t)bb*NN*32;
    __half* PA = P;
    __half* PB = P + 64*PSTR;
    uint2* mt = mt_all + w*32;

    // ---- phase 1: gather + pool ----
    for (int qq = 0; qq < 8; qq++) {
        int pl = w*8 + qq;
        int p  = pt0 + pl;
        {
            int fi = nidx[(size_t)p*KK + L];
            const float* ep = ef + (size_t)p*96 + 3*L;
            __half2 e01 = __floats2half2_rn(ep[0], ep[1]);
            unsigned e2b = (unsigned)__half_as_ushort(__float2half_rn(ep[2]));
            mt[L] = make_uint2((unsigned)fi | (e2b << 16), *(const unsigned*)&e01);
        }
        __syncwarp();
        __half2 ma = __float2half2_rn(-6.0e4f), mb = ma;
        #pragma unroll 8
        for (int k = 0; k < KK; k++) {
            uint2 m = mt[k];
            int fi = (int)(m.x & 0xFFFFu);
            __half2 h2v = __half2half2(__ushort_as_half((unsigned short)(m.x >> 16)));
            __half2 e01 = *(const __half2*)&m.y;
            __half2 h0 = __low2half2(e01), h1 = __high2half2(e01);
            uint2 v = __ldg(&Fab[(size_t)fi*32 + L]);
            __half2 ta = *(const __half2*)&v.x;
            ta = __hfma2(h0, wA[0], ta);
            ta = __hfma2(h1, wA[1], ta);
            ta = __hfma2(h2v, wA[2], ta);
            ma = __hmax2(ma, ta);
            __half2 tb = *(const __half2*)&v.y;
            tb = __hfma2(h0, wB[0], tb);
            tb = __hfma2(h1, wB[1], tb);
            tb = __hfma2(h2v, wB[2], tb);
            mb = __hmax2(mb, tb);
        }
        __syncwarp();
        float2 fa = __half22float2(ma), fb = __half22float2(mb);
        fa.x = lrelu(fa.x + b1a.x);  fa.y = lrelu(fa.y + b1a.y);
        fb.x = lrelu(fb.x + b1b.x);  fb.y = lrelu(fb.y + b1b.y);
        *(__half2*)&PA[pl*PSTR + 2*L] = __floats2half2_rn(fa.x, fa.y);
        *(__half2*)&PB[pl*PSTR + 2*L] = __floats2half2_rn(fb.x, fb.y);
    }
    __syncthreads();

    // ---- phase 2: MLP on tensor pipe ----
    int wbr = w >> 2, wm = w & 3;        // 4 m-warps per branch
    __half* Pb  = P   + wbr*64*PSTR;
    __half* W2b = sW2 + wbr*64*PSTR;
    __half* W3b = sW3 + wbr*64*PSTR;
    int r = L >> 2, cq = (L & 3) * 2;
    const float* b2v = b2 + wbr*64;
    const float* b3v = b3 + wbr*64;

    // layer 1
    float C[8][4];
    #pragma unroll
    for (int i = 0; i < 8; i++)
        #pragma unroll
        for (int j = 0; j < 4; j++) C[i][j] = 0.f;
    #pragma unroll
    for (int ks = 0; ks < 4; ks++) {
        int k0 = ks * 16;
        unsigned a0,a1,a2,a3;
        ldsm_x4(a0,a1,a2,a3, sm_u32(&Pb[(wm*16 + (L&15))*PSTR + k0 + (L>>4)*8]));
        #pragma unroll
        for (int nt = 0; nt < 4; nt++) {
            unsigned b0v,b1v,b2q,b3q;
            ldsm_x4_t(b0v,b1v,b2q,b3q,
                sm_u32(&W2b[(k0 + (L&15))*PSTR + nt*16 + (L>>4)*8]));
            mma16816(C[2*nt],   a0,a1,a2,a3, b0v,b1v);
            mma16816(C[2*nt+1], a0,a1,a2,a3, b2q,b3q);
        }
    }
    __syncthreads();   // all ldsm of P complete -> safe to overwrite
    #pragma unroll
    for (int nt8 = 0; nt8 < 8; nt8++) {
        int col = nt8*8 + cq;
        float c0 = lrelu(C[nt8][0] + __ldg(&b2v[col]));
        float c1 = lrelu(C[nt8][1] + __ldg(&b2v[col+1]));
        float c2 = lrelu(C[nt8][2] + __ldg(&b2v[col]));
        float c3 = lrelu(C[nt8][3] + __ldg(&b2v[col+1]));
        *(__half2*)&Pb[(wm*16 + r)*PSTR + col]     = __floats2half2_rn(c0, c1);
        *(__half2*)&Pb[(wm*16 + r + 8)*PSTR + col] = __floats2half2_rn(c2, c3);
    }
    __syncthreads();

    // layer 2
    #pragma unroll
    for (int i = 0; i < 8; i++)
        #pragma unroll
        for (int j = 0; j < 4; j++) C[i][j] = 0.f;
    #pragma unroll
    for (int ks = 0; ks < 4; ks++) {
        int k0 = ks * 16;
        unsigned a0,a1,a2,a3;
        ldsm_x4(a0,a1,a2,a3, sm_u32(&Pb[(wm*16 + (L&15))*PSTR + k0 + (L>>4)*8]));
        #pragma unroll
        for (int nt = 0; nt < 4; nt++) {
            unsigned b0v,b1v,b2q,b3q;
            ldsm_x4_t(b0v,b1v,b2q,b3q,
                sm_u32(&W3b[(k0 + (L&15))*PSTR + nt*16 + (L>>4)*8]));
            mma16816(C[2*nt],   a0,a1,a2,a3, b0v,b1v);
            mma16816(C[2*nt+1], a0,a1,a2,a3, b2q,b3q);
        }
    }
    // final epilogue
    #pragma unroll
    for (int nt8 = 0; nt8 < 8; nt8++) {
        int col = nt8*8 + cq;
        int pLo = pt0 + wm*16 + r;
        int pHi = pLo + 8;
        float c0 = sigm(C[nt8][0] + __ldg(&b3v[col]));
        float c1 = sigm(C[nt8][1] + __ldg(&b3v[col+1]));
        float c2 = sigm(C[nt8][2] + __ldg(&b3v[col]));
        float c3 = sigm(C[nt8][3] + __ldg(&b3v[col+1]));
        if (wbr == 0) {
            *(float2*)&z_out[(size_t)pLo*64 + col] = make_float2(c0, c1);
            *(float2*)&z_out[(size_t)pHi*64 + col] = make_float2(c2, c3);
        } else {
            float2 hLo = *(const float2*)&h[(size_t)pLo*64 + col];
            float2 hHi = *(const float2*)&h[(size_t)pHi*64 + col];
            *(float2*)&rh_out[(size_t)pLo*64 + col] = make_float2(c0*hLo.x, c1*hLo.y);
            *(float2*)&rh_out[(size_t)pHi*64 + col] = make_float2(c2*hHi.x, c3*hHi.y);
        }
    }
}

// ---------------- gate2 (HMMA MLP): branch 2 -> q; out = h + z*(q-h) ----------------
// tile = 64 points, 8 warps: gather 8 pts/warp, MLP = 4 m-bands x 2 n-halves.
__global__ void __launch_bounds__(256)
gate2_hmma(const float* __restrict__ h,
    const float* __restrict__ W1, const float* __restrict__ b1,
    const float* __restrict__ W2, const float* __restrict__ b2,
    const float* __restrict__ W3, const float* __restrict__ b3,
    const int* __restrict__ nidx, const float* __restrict__ ef,
    float* __restrict__ out)
{
    extern __shared__ __half smh[];
    __half* sW2 = smh;                 // [64 x PSTR]
    __half* sW3 = smh + 64*PSTR;       // [64 x PSTR]
    __half* P   = smh + 2*64*PSTR;     // [64 x PSTR]
    uint2* mt_all = (uint2*)(smh + 3*64*PSTR);
    int tid = threadIdx.x, w = tid>>5, L = tid&31;

    for (int i = tid; i < 64*64; i += 256) {
        int j = i >> 6, d = i & 63;
        sW2[j*PSTR + d] = __float2half_rn(W2[2*4096 + j*64 + d]);
        sW3[j*PSTR + d] = __float2half_rn(W3[2*4096 + j*64 + d]);
    }
    __syncthreads();

    const float* eWc = W1 + 2*131*64 + 128*64;
    __half2 wC[3];
    #pragma unroll
    for (int j = 0; j < 3; j++)
        wC[j] = __floats2half2_rn(eWc[j*64 + 2*L], eWc[j*64 + 2*L + 1]);
    float2 b1c = *(const float2*)&b1[128 + 2*L];

    int pt0 = blockIdx.x * 64;
    int bb = pt0 >> 13;
    const __half2* Fc = g_F1c + (size_t)bb*NN*32;
    uint2* mt = mt_all + w*32;

    // ---- phase 1: gather + pool (8 pts per warp) ----
    for (int qq = 0; qq < 8; qq++) {
        int pl = w*8 + qq;
        int p  = pt0 + pl;
        {
            int fi = nidx[(size_t)p*KK + L];
            const float* ep = ef + (size_t)p*96 + 3*L;
            __half2 e01 = __floats2half2_rn(ep[0], ep[1]);
            unsigned e2b = (unsigned)__half_as_ushort(__float2half_rn(ep[2]));
            mt[L] = make_uint2((unsigned)fi | (e2b << 16), *(const unsigned*)&e01);
        }
        __syncwarp();
        __half2 mc = __float2half2_rn(-6.0e4f);
        #pragma unroll 8
        for (int k = 0; k < KK; k++) {
            uint2 m = mt[k];
            int fi = (int)(m.x & 0xFFFFu);
            __half2 h2v = __half2half2(__ushort_as_half((unsigned short)(m.x >> 16)));
            __half2 e01 = *(const __half2*)&m.y;
            __half2 h0 = __low2half2(e01), h1 = __high2half2(e01);
            __half2 v = __ldg(&Fc[(size_t)fi*32 + L]);
            v = __hfma2(h0, wC[0], v);
            v = __hfma2(h1, wC[1], v);
            v = __hfma2(h2v, wC[2], v);
            mc = __hmax2(mc, v);
        }
        __syncwarp();
        float2 fc = __half22float2(mc);
        fc.x = lrelu(fc.x + b1c.x);  fc.y = lrelu(fc.y + b1c.y);
        *(__half2*)&P[pl*PSTR + 2*L] = __floats2half2_rn(fc.x, fc.y);
    }
    __syncthreads();

    // ---- phase 2: MLP (M=64, 4 m-bands x 2 n-halves over 8 warps) ----
    int wm = w >> 1, wn = w & 1;
    int r = L >> 2, cq = (L & 3) * 2;
    const float* b2v = b2 + 128;
    const float* b3v = b3 + 128;

    float C[4][4];
    #pragma unroll
    for (int i = 0; i < 4; i++)
        #pragma unroll
        for (int j = 0; j < 4; j++) C[i][j] = 0.f;
    #pragma unroll
    for (int ks = 0; ks < 4; ks++) {
        int k0 = ks * 16;
        unsigned a0,a1,a2,a3;
        ldsm_x4(a0,a1,a2,a3, sm_u32(&P[(wm*16 + (L&15))*PSTR + k0 + (L>>4)*8]));
        #pragma unroll
        for (int nt = 0; nt < 2; nt++) {
            unsigned b0v,b1v,b2q,b3q;
            ldsm_x4_t(b0v,b1v,b2q,b3q,
                sm_u32(&sW2[(k0 + (L&15))*PSTR + wn*32 + nt*16 + (L>>4)*8]));
            mma16816(C[2*nt],   a0,a1,a2,a3, b0v,b1v);
            mma16816(C[2*nt+1], a0,a1,a2,a3, b2q,b3q);
        }
    }
    __syncthreads();
    #pragma unroll
    for (int nt4 = 0; nt4 < 4; nt4++) {
        int col = wn*32 + nt4*8 + cq;
        float c0 = lrelu(C[nt4][0] + __ldg(&b2v[col]));
        float c1 = lrelu(C[nt4][1] + __ldg(&b2v[col+1]));
        float c2 = lrelu(C[nt4][2] + __ldg(&b2v[col]));
        float c3 = lrelu(C[nt4][3] + __ldg(&b2v[col+1]));
        *(__half2*)&P[(wm*16 + r)*PSTR + col]     = __floats2half2_rn(c0, c1);
        *(__half2*)&P[(wm*16 + r + 8)*PSTR + col] = __floats2half2_rn(c2, c3);
    }
    __syncthreads();

    #pragma unroll
    for (int i = 0; i < 4; i++)
        #pragma unroll
        for (int j = 0; j < 4; j++) C[i][j] = 0.f;
    #pragma unroll
    for (int ks = 0; ks < 4; ks++) {
        int k0 = ks * 16;
        unsigned a0,a1,a2,a3;
        ldsm_x4(a0,a1,a2,a3, sm_u32(&P[(wm*16 + (L&15))*PSTR + k0 + (L>>4)*8]));
        #pragma unroll
        for (int nt = 0; nt < 2; nt++) {
            unsigned b0v,b1v,b2q,b3q;
            ldsm_x4_t(b0v,b1v,b2q,b3q,
                sm_u32(&sW3[(k0 + (L&15))*PSTR + wn*32 + nt*16 + (L>>4)*8]));
            mma16816(C[2*nt],   a0,a1,a2,a3, b0v,b1v);
            mma16816(C[2*nt+1], a0,a1,a2,a3, b2q,b3q);
        }
    }
    #pragma unroll
    for (int nt4 = 0; nt4 < 4; nt4++) {
        int col = wn*32 + nt4*8 + cq;
        int pLo = pt0 + wm*16 + r;
        int pHi = pLo + 8;
        float q0 = tanhf(C[nt4][0] + __ldg(&b3v[col]));
        float q1 = tanhf(C[nt4][1] + __ldg(&b3v[col+1]));
        float q2 = tanhf(C[nt4][2] + __ldg(&b3v[col]));
        float q3 = tanhf(C[nt4][3] + __ldg(&b3v[col+1]));
        float2 zLo = *(const float2*)&g_z[(size_t)pLo*64 + col];
        float2 zHi = *(const float2*)&g_z[(size_t)pHi*64 + col];
        float2 hLo = *(const float2*)&h[(size_t)pLo*64 + col];
        float2 hHi = *(const float2*)&h[(size_t)pHi*64 + col];
        *(float2*)&out[(size_t)pLo*64 + col] =
            make_float2(hLo.x + zLo.x*(q0 - hLo.x), hLo.y + zLo.y*(q1 - hLo.y));
        *(float2*)&out[(size_t)pHi*64 + col] =
            make_float2(hHi.x + zHi.x*(q2 - hHi.x), hHi.y + zHi.y*(q3 - hHi.y));
    }
}

extern "C" void kernel_launch(void* const* d_in, const int* in_sizes, int n_in,
                              void* d_out, int out_size)
{
    const float* h   = (const float*)d_in[0];
    const float* x   = (const float*)d_in[1];
    // d_in[2] = c, unused (matches reference)
    const float* W1  = (const float*)d_in[3];
    const float* b1  = (const float*)d_in[4];
    const float* W2  = (const float*)d_in[5];
    const float* b2  = (const float*)d_in[6];
    const float* W3  = (const float*)d_in[7];
    const float* b3  = (const float*)d_in[8];
    const int*   nidx = (const int*)d_in[9];
    const float* ef  = (const float*)d_in[10];
    float* out = (float*)d_out;

    void *pF1ab, *pF1c, *pz, *prh;
    cudaGetSymbolAddress(&pF1ab, g_F1ab);
    cudaGetSymbolAddress(&pF1c,  g_F1c);
    cudaGetSymbolAddress(&pz,    g_z);
    cudaGetSymbolAddress(&prh,   g_rh);

    const int smem_l2h = (64*ASTR + 128*B2STR) * 2;        // 52224 B
    const int smem_l1h = (64*ASTR + 128*B1STR) * 2;        // 35840 B
    const int smem_g01 = 6*64*PSTR*2 + 8*32*8;             // 57344 B
    const int smem_g2  = 3*64*PSTR*2 + 8*32*8;             // 29696 B

    cudaFuncSetAttribute(linear2_hmma, cudaFuncAttributeMaxDynamicSharedMemorySize, smem_l2h);
    cudaFuncSetAttribute(linear1_hmma, cudaFuncAttributeMaxDynamicSharedMemorySize, smem_l1h);
    cudaFuncSetAttribute(gate01_hmma,  cudaFuncAttributeMaxDynamicSharedMemorySize, smem_g01);
    cudaFuncSetAttribute(gate2_hmma,   cudaFuncAttributeMaxDynamicSharedMemorySize, smem_g2);

    dim3 blk(256);

    // F1ab = [h|x] @ {W1a[0], W1a[1]}  (HMMA, packed fp16 out)
    linear2_hmma<<<296, blk, smem_l2h>>>(h, x, W1, (unsigned*)pF1ab);
    // z, r*h  (512 tiles of 64 points)
    gate01_hmma<<<512, blk, smem_g01>>>(h, W1, b1, W2, b2, W3, b3, nidx, ef,
                                        (float*)pz, (float*)prh);
    // F1c = [r*h|x] @ W1a[2]  (HMMA, fp16 out)
    linear1_hmma<<<296, blk, smem_l1h>>>((const float*)prh, x, W1, (unsigned*)pF1c);
    // q and final output  (512 tiles of 64 points)
    gate2_hmma<<<512, blk, smem_g2>>>(h, W1, b1, W2, b2, W3, b3, nidx, ef, out);
}